// round 10
// baseline (speedup 1.0000x reference)
#include <cuda_runtime.h>
#include <math.h>
#include <stdint.h>

// Problem constants
#define BB_ 32
#define NN_ 49
#define DD_ 512
#define MM_ (BB_*NN_)      // 1568
#define NRELV_ 14
#define EPSV_ 1e-5f
#define SCALEV_ 0.125f     // 1/sqrt(64)

// ---------------- device scratch (no allocations allowed) ----------------
__device__ __align__(256) float g_hconv[MM_*DD_];
__device__ __align__(256) float g_hpart[9*MM_*DD_];   // split-K partials (no atomics)
__device__ __align__(256) float g_qr[MM_*DD_];
__device__ __align__(256) float g_eq[MM_*DD_];
__device__ __align__(256) float g_ek[MM_*DD_];
__device__ __align__(256) float g_ev[MM_*DD_];
__device__ __align__(256) float g_eqcat[MM_*1280];
__device__ __align__(256) float g_ekcat[MM_*1280];
__device__ __align__(256) float g_v[MM_*DD_];
__device__ __align__(256) float g_att[MM_*DD_];
__device__ __align__(256) float g_convWt[9*512*512];
__device__ __align__(256) float g_Bq[512*1280];
__device__ __align__(256) float g_Bk[512*1280];
__device__ __align__(256) float g_Wvr[512*512];
__device__ __align__(256) float g_Wor[512*512];
__device__ __align__(256) float g_biasq[1280];
__device__ __align__(256) float g_biask[1280];
__device__ float g_sums[1024];
__device__ float g_wr2g[512];
__device__ float g_reg[NRELV_];
__device__ float g_c0[1];
__device__ float g_gate[MM_*NN_];
__device__ unsigned g_bar1 = 0;
__device__ unsigned g_bar2 = 0;

__device__ __forceinline__ float wsum(float v) {
#pragma unroll
    for (int o = 16; o > 0; o >>= 1) v += __shfl_xor_sync(0xffffffffu, v, o);
    return v;
}

__device__ __forceinline__ float to_tf32(float x) {
    uint32_t u;
    asm("cvt.rna.tf32.f32 %0, %1;" : "=r"(u) : "f"(x));
    return __uint_as_float(u);
}

__device__ __forceinline__ void mma_tf32(float* c,
                                         uint32_t a0, uint32_t a1, uint32_t a2, uint32_t a3,
                                         uint32_t b0, uint32_t b1) {
    asm volatile("mma.sync.aligned.m16n8k8.row.col.f32.tf32.tf32.f32 "
                 "{%0,%1,%2,%3}, {%4,%5,%6,%7}, {%8,%9}, {%0,%1,%2,%3};"
                 : "+f"(c[0]), "+f"(c[1]), "+f"(c[2]), "+f"(c[3])
                 : "r"(a0), "r"(a1), "r"(a2), "r"(a3), "r"(b0), "r"(b1));
}

__device__ __forceinline__ void cp16(uint32_t dst, const float* src, bool pred) {
    int sz = pred ? 16 : 0;
    asm volatile("cp.async.cg.shared.global [%0], [%1], 16, %2;\n"
                 :: "r"(dst), "l"(src), "r"(sz));
}
#define CP_COMMIT() asm volatile("cp.async.commit_group;" ::: "memory")
#define CP_WAIT1()  asm volatile("cp.async.wait_group 1;" ::: "memory")

// ---------------- fused prologue: conv repack + Q round + k0 + bcat ----------
__global__ void __launch_bounds__(256)
rea_prologue(const float* __restrict__ convW, const float* __restrict__ Q,
             const float* __restrict__ Wr2, const float* __restrict__ Wproj,
             const float* __restrict__ Wg, const float* __restrict__ rel,
             const float* __restrict__ br2, const float* __restrict__ bproj,
             const float* __restrict__ bgate,
             const float* __restrict__ Wq, const float* __restrict__ Wk,
             const float* __restrict__ Wc1, const float* __restrict__ Wr1,
             const float* __restrict__ bq, const float* __restrict__ bk,
             const float* __restrict__ Wv, const float* __restrict__ Wo) {
    int bx = blockIdx.x, t = threadIdx.x;
    if (bx < 256) {
        __shared__ float ts[32*289];
        int o0 = (bx & 15)*32, c0 = (bx >> 4)*32;
        for (int idx = t; idx < 32*288; idx += 256) {
            int o = idx / 288, r = idx - o*288;   // r = c_local*9 + tap
            ts[o*289 + r] = to_tf32(convW[((size_t)(o0 + o)*512 + c0)*9 + r]);
        }
        __syncthreads();
        for (int idx = t; idx < 288*32; idx += 256) {
            int row = idx >> 5, o = idx & 31;
            int c = row / 9, tap = row - c*9;
            g_convWt[(size_t)tap*262144 + (size_t)(c0 + c)*512 + o0 + o] = ts[o*289 + row];
        }
    } else if (bx < 1040) {
        int idx = (bx - 256)*256 + t;
        if (idx < MM_*DD_/4) {
            float4 qv = ((const float4*)Q)[idx];
            float4 r;
            r.x = to_tf32(qv.x); r.y = to_tf32(qv.y);
            r.z = to_tf32(qv.z); r.w = to_tf32(qv.w);
            ((float4*)g_qr)[idx] = r;
        }
        if (bx == 256)
            ((float4*)g_sums)[t] = make_float4(0.f, 0.f, 0.f, 0.f);
    } else if (bx < 1105) {
        __shared__ float wg_s[512];
        __shared__ float wpg_s[64];
        int kb = bx - 1040;
        wg_s[t] = Wg[t];
        wg_s[t + 256] = Wg[t + 256];
        __syncthreads();
        int w = t >> 5, l = t & 31;
        if (kb < 64) {
            int row = kb*8 + w;
            float s = 0.f;
            for (int j = l; j < 512; j += 32) s += Wr2[(size_t)row*512 + j] * wg_s[j];
            s = wsum(s);
            if (l == 0) g_wr2g[row] = s;
        } else {
            for (int r = w; r < 64; r += 8) {
                float s = 0.f;
                for (int j = l; j < 512; j += 32) s += Wproj[(size_t)r*512 + j] * wg_s[j];
                s = wsum(s);
                if (l == 0) wpg_s[r] = s;
            }
            __syncthreads();
            if (t < NRELV_) {
                float s = 0.f;
                for (int d = 0; d < 64; d++) s += rel[t*64 + d] * wpg_s[d];
                g_reg[t] = s;
            }
            if (w == 7) {
                float s = 0.f;
                for (int j = l; j < 512; j += 32) s += (br2[j] + bproj[j]) * wg_s[j];
                s = wsum(s);
                if (l == 0) g_c0[0] = s + bgate[0];
            }
        }
    } else {
        int idx = (bx - 1105)*256 + t;
        if (idx < 512*1280) {
            int k = idx / 1280, n = idx - k*1280;
            float vq, vk;
            if (n < 512)       { vq = Wq[(size_t)k*512 + n];              vk = Wk[(size_t)k*512 + n]; }
            else if (n < 768)  { vq = Wc1[(size_t)k*256 + (n-512)];       vk = Wc1[(size_t)(k+512)*256 + (n-512)]; }
            else               { vq = Wr1[(size_t)k*512 + (n-768)];       vk = Wr1[(size_t)(k+512)*512 + (n-768)]; }
            g_Bq[idx] = to_tf32(vq); g_Bk[idx] = to_tf32(vk);
        }
        if (idx < 512*512) {
            g_Wvr[idx] = to_tf32(Wv[idx]);
            g_Wor[idx] = to_tf32(Wo[idx]);
        }
        if (idx < 1280) {
            g_biasq[idx] = idx < 512 ? bq[idx] : 0.f;
            g_biask[idx] = idx < 512 ? bk[idx] : 0.f;
        }
    }
}

// ---------------- TF32 tensor-core GEMM core ----------------
// 128 threads = 4 warps (2M x 2N), warp tile 64x64, block tile 128x128, BK=32,
// 3-stage cp.async ring.
#define BMT 128
#define BNT 128
#define BKT 32
#define APAD 36
#define BPAD 136
#define SZA (BMT*APAD*4)
#define SZB (BKT*BPAD*4)
#define GEMM_SMEM (3*(BMT*APAD + BKT*BPAD)*4)

template <bool CONV, bool ATOMIC>
__device__ __forceinline__ void gemm_core(
    const float* __restrict__ A, const float* __restrict__ Bm,
    const float* __restrict__ bias, float* __restrict__ C,
    int M, int N, int lda, int kbase, int KT, int di, int dj,
    int m0, int n0, int zz,
    float* AsB, float* BsB) {

    int tid = threadIdx.x;
    int lane = tid & 31, warp = tid >> 5;
    int g = lane >> 2, t4 = lane & 3;
    int wm = (warp & 1) * 64, wn = (warp >> 1) * 64;

    uint32_t sA = (uint32_t)__cvta_generic_to_shared(AsB);
    uint32_t sB = (uint32_t)__cvta_generic_to_shared(BsB);

    float acc[4][8][4];
#pragma unroll
    for (int i = 0; i < 4; i++)
#pragma unroll
        for (int j = 0; j < 8; j++)
#pragma unroll
            for (int q = 0; q < 4; q++) acc[i][j][q] = 0.f;

    const float* aptr[8]; bool apred[8]; uint32_t adst[8];
    const float* bptr0; uint32_t bdst0;
#pragma unroll
    for (int h = 0; h < 8; h++) {
        int c = tid + h*128;
        int m = c >> 3, kg = c & 7;
        int gm = m0 + m;
        bool pred;
        const float* p;
        if (!CONV) {
            pred = gm < M;
            p = A + (size_t)(pred ? gm : 0)*lda + kbase + kg*4;
        } else {
            int bb = gm / 49, pos = gm - bb*49;
            int pr = pos / 7, pc = pos - pr*7;
            int ii = pr + di, jj = pc + dj;
            pred = (gm < M) & ((unsigned)ii < 7u) & ((unsigned)jj < 7u);
            p = pred ? (A + ((size_t)(bb*49 + ii*7 + jj))*512 + kg*4) : A;
        }
        apred[h] = pred; aptr[h] = p;
        adst[h] = sA + (uint32_t)(m*APAD + kg*4)*4;
    }
    {
        int kr = tid >> 5, ng = tid & 31;
        bptr0 = Bm + (size_t)(kbase + kr)*N + n0 + ng*4;
        bdst0 = sB + (uint32_t)(kr*BPAD + ng*4)*4;
    }

    auto load_tile = [&](int kt, int buf) {
#pragma unroll
        for (int h = 0; h < 8; h++)
            cp16(adst[h] + buf*SZA, aptr[h] + kt*BKT, apred[h]);
#pragma unroll
        for (int h = 0; h < 8; h++)
            cp16(bdst0 + buf*SZB + (uint32_t)h*4*BPAD*4,
                 bptr0 + (size_t)(kt*BKT + h*4)*N, true);
    };

    load_tile(0, 0); CP_COMMIT();
    if (KT > 1) load_tile(1, 1);
    CP_COMMIT();

    int buf = 0, nbuf = 2;
    for (int kt = 0; kt < KT; kt++) {
        CP_WAIT1();
        __syncthreads();
        if (kt + 2 < KT) load_tile(kt + 2, nbuf);
        CP_COMMIT();
        const float* as = AsB + buf*(BMT*APAD);
        const float* bs = BsB + buf*(BKT*BPAD);
#pragma unroll
        for (int k8 = 0; k8 < 4; k8++) {
            uint32_t af[4][4], bf[8][2];
#pragma unroll
            for (int i = 0; i < 4; i++) {
                int mrow = wm + i*16 + g;
                af[i][0] = __float_as_uint(as[mrow*APAD + k8*8 + t4]);
                af[i][1] = __float_as_uint(as[(mrow + 8)*APAD + k8*8 + t4]);
                af[i][2] = __float_as_uint(as[mrow*APAD + k8*8 + t4 + 4]);
                af[i][3] = __float_as_uint(as[(mrow + 8)*APAD + k8*8 + t4 + 4]);
            }
#pragma unroll
            for (int j = 0; j < 8; j++) {
                int nc = wn + j*8 + g;
                bf[j][0] = __float_as_uint(bs[(k8*8 + t4)*BPAD + nc]);
                bf[j][1] = __float_as_uint(bs[(k8*8 + t4 + 4)*BPAD + nc]);
            }
#pragma unroll
            for (int i = 0; i < 4; i++)
#pragma unroll
                for (int j = 0; j < 8; j++)
                    mma_tf32(acc[i][j], af[i][0], af[i][1], af[i][2], af[i][3],
                             bf[j][0], bf[j][1]);
        }
        buf = (buf == 2) ? 0 : buf + 1;
        nbuf = (nbuf == 2) ? 0 : nbuf + 1;
    }

#pragma unroll
    for (int i = 0; i < 4; i++) {
        int mbase = m0 + wm + i*16 + g;
#pragma unroll
        for (int half = 0; half < 2; half++) {
            int gm = mbase + half*8;
            if (gm < M) {
#pragma unroll
                for (int j = 0; j < 8; j++) {
                    int gn = n0 + wn + j*8 + t4*2;
                    float v0 = acc[i][j][half*2 + 0];
                    float v1 = acc[i][j][half*2 + 1];
                    if (ATOMIC) {
                        if (zz == 0 && bias) { v0 += bias[gn]; v1 += bias[gn + 1]; }
                        atomicAdd(&C[(size_t)gm*N + gn],     v0);
                        atomicAdd(&C[(size_t)gm*N + gn + 1], v1);
                    } else {
                        if (bias) { v0 += bias[gn]; v1 += bias[gn + 1]; }
                        C[(size_t)gm*N + gn]     = v0;
                        C[(size_t)gm*N + gn + 1] = v1;
                    }
                }
            }
        }
    }
}

extern __shared__ float sm_gemm[];

// conv as implicit GEMM, split-K=9 (one tap per z), plain stores to partials
__global__ void __launch_bounds__(128, 2)
rea_gconv(const float* __restrict__ A, const float* __restrict__ Bm) {
    int tap = blockIdx.z;
    float* Cp = g_hpart + (size_t)tap*MM_*512;
    gemm_core<true, false>(A, Bm, nullptr, Cp, MM_, 512, 512,
                           tap*512, 16, tap/3 - 1, tap%3 - 1,
                           blockIdx.y*BMT, blockIdx.x*BNT, tap,
                           sm_gemm, sm_gemm + 3*BMT*APAD);
}

// batched eq/ek/ev projections, split-K=2 (624 blocks), atomic accumulate
__global__ void __launch_bounds__(128, 2)
rea_gqkv(const float* __restrict__ bv) {
    int bx = blockIdx.x;
    int sk = bx & 1;
    int tid2 = bx >> 1;            // 0..311
    int z, lx;
    if (tid2 < 130)      { z = 0; lx = tid2; }
    else if (tid2 < 260) { z = 1; lx = tid2 - 130; }
    else                 { z = 2; lx = tid2 - 260; }
    int m0, n0;
    if (z < 2) { n0 = (lx % 10)*BNT; m0 = (lx / 10)*BMT; }
    else       { n0 = (lx & 3)*BNT;  m0 = (lx >> 2)*BMT; }
    const float* A    = z == 0 ? g_eq    : z == 1 ? g_ek    : g_ev;
    const float* Bm   = z == 0 ? g_Bq    : z == 1 ? g_Bk    : g_Wvr;
    const float* bias = z == 0 ? g_biasq : z == 1 ? g_biask : bv;
    float*       C    = z == 0 ? g_eqcat : z == 1 ? g_ekcat : g_v;
    int N = z < 2 ? 1280 : 512;
    gemm_core<false, true>(A, Bm, bias, C, MM_, N, 512, sk*256, 8, 0, 0,
                           m0, n0, sk, sm_gemm, sm_gemm + 3*BMT*APAD);
}

// output projection, split-K=4, atomic into pre-zeroed d_out
__global__ void __launch_bounds__(128, 2)
rea_gout(const float* __restrict__ A, const float* __restrict__ Bm,
         const float* __restrict__ bias, float* __restrict__ C) {
    gemm_core<false, true>(A, Bm, bias, C, MM_, 512, 512,
                           blockIdx.z*128, 4, 0, 0,
                           blockIdx.y*BMT, blockIdx.x*BNT, blockIdx.z,
                           sm_gemm, sm_gemm + 3*BMT*APAD);
}

// ---------------- fused: conv-partial reduce + BN stats | barrier | eqkv -----
// 296 blocks x 256 threads. All blocks resident (no smem, low regs) so the
// device-wide spin barrier cannot deadlock. Counters self-reset for replay.
__global__ void __launch_bounds__(256)
rea_bneqkv(const float* __restrict__ convb, const float* __restrict__ Q,
           const float* __restrict__ Kin, const float* __restrict__ Vin) {
    int t = threadIdx.x;
    // ---- phase A: reduce 9 partials + bias -> hconv, accumulate BN stats ----
    for (int gb = blockIdx.x; gb < 98; gb += 296) {
        int c4 = t & 127;
        int rh = t >> 7;
        int r0 = gb*16;
        float4 cb = ((const float4*)convb)[c4];
        float4 s1 = make_float4(0.f, 0.f, 0.f, 0.f);
        float4 s2 = make_float4(0.f, 0.f, 0.f, 0.f);
#pragma unroll
        for (int it = 0; it < 8; it++) {
            int r = r0 + it*2 + rh;
            size_t off = (size_t)r*128 + c4;
            float4 a = cb;
#pragma unroll
            for (int tp = 0; tp < 9; tp++) {
                float4 p = ((const float4*)g_hpart)[(size_t)tp*(MM_*128) + off];
                a.x += p.x; a.y += p.y; a.z += p.z; a.w += p.w;
            }
            ((float4*)g_hconv)[off] = a;
            s1.x += a.x; s1.y += a.y; s1.z += a.z; s1.w += a.w;
            s2.x = fmaf(a.x, a.x, s2.x); s2.y = fmaf(a.y, a.y, s2.y);
            s2.z = fmaf(a.z, a.z, s2.z); s2.w = fmaf(a.w, a.w, s2.w);
        }
        int c = c4*4;
        atomicAdd(&g_sums[c + 0], s1.x); atomicAdd(&g_sums[c + 1], s1.y);
        atomicAdd(&g_sums[c + 2], s1.z); atomicAdd(&g_sums[c + 3], s1.w);
        atomicAdd(&g_sums[512 + c + 0], s2.x); atomicAdd(&g_sums[512 + c + 1], s2.y);
        atomicAdd(&g_sums[512 + c + 2], s2.z); atomicAdd(&g_sums[512 + c + 3], s2.w);
    }
    // ---- device-wide barrier ----
    __syncthreads();
    __threadfence();
    if (t == 0) {
        atomicAdd(&g_bar1, 1u);
        while (atomicAdd(&g_bar1, 0u) < 296u) { }
    }
    __syncthreads();
    // ---- phase B: eqkv + zero the atomic-accumulated GEMM outputs ----
    int gstep = 296*256;
    for (int idx = blockIdx.x*256 + t; idx < MM_*DD_/4; idx += gstep) {
        int c = (idx*4) & 511;
        float4 sm = *(const float4*)&g_sums[c];
        float4 sq = *(const float4*)&g_sums[512 + c];
        float4 hv = ((const float4*)g_hconv)[idx];
        float4 qv = ((const float4*)Q)[idx];
        float4 kv = ((const float4*)Kin)[idx];
        float4 vv = ((const float4*)Vin)[idx];
        float4 eq, ek, ev;
#define BN1(comp) { \
        float mu = sm.comp * (1.f/1568.f); \
        float var = sq.comp * (1.f/1568.f) - mu*mu; \
        float xn = fmaxf((hv.comp - mu) * rsqrtf(var + EPSV_), 0.f); \
        eq.comp = to_tf32(xn + qv.comp); \
        ek.comp = to_tf32(xn + kv.comp); \
        ev.comp = to_tf32(xn + vv.comp); }
        BN1(x) BN1(y) BN1(z) BN1(w)
#undef BN1
        ((float4*)g_eq)[idx] = eq;
        ((float4*)g_ek)[idx] = ek;
        ((float4*)g_ev)[idx] = ev;
    }
    float4 z4 = make_float4(0.f, 0.f, 0.f, 0.f);
    for (int idx = blockIdx.x*256 + t; idx < MM_*1280/4; idx += gstep) {
        ((float4*)g_eqcat)[idx] = z4;
        ((float4*)g_ekcat)[idx] = z4;
    }
    for (int idx = blockIdx.x*256 + t; idx < MM_*512/4; idx += gstep)
        ((float4*)g_v)[idx] = z4;
    // ---- reset barrier counters for next graph replay ----
    __syncthreads();
    if (t == 0) {
        unsigned v = atomicAdd(&g_bar2, 1u);
        if (v == 295u) { g_bar1 = 0u; g_bar2 = 0u; __threadfence(); }
    }
}

// ---------------- per-pair gate: one pair per LANE, j-dim tiled in smem ------
#define PTILE 64
__global__ void __launch_bounds__(512)
rea_pair(const float* __restrict__ Wc2, const float* __restrict__ bc1,
         const float* __restrict__ gc, const float* __restrict__ bcln,
         const float* __restrict__ bc2, const float* __restrict__ br1,
         const float* __restrict__ gr, const float* __restrict__ brln) {
    __shared__ float ck_s[PTILE*49];
    __shared__ float pq_s[PTILE*49];
    __shared__ float wct_s[PTILE*16];
    __shared__ float2 ab_s[PTILE];
    __shared__ float w2_s[PTILE];
    __shared__ float s_bc2[16], s_reg[16];

    int b = blockIdx.x;
    int t = threadIdx.x;
    int p = blockIdx.y*512 + t;
    int q = p / 49, k = p - q*49;
    bool act = q < 49;
    int qc = act ? q : 48;
    int b49 = b*49;

    if (t < NRELV_) { s_bc2[t] = bc2[t]; s_reg[t] = g_reg[t]; }
    if (t < PTILE) { wct_s[t*16 + 14] = 0.f; wct_s[t*16 + 15] = 0.f; }

    // ======== channel branch (256 dims, offset 512) ========
    float s1 = 0.f, s2 = 0.f;
    for (int jt = 0; jt < 4; jt++) {
        int j0 = jt*PTILE;
        __syncthreads();
        for (int idx = t; idx < PTILE*49; idx += 512) {
            int kk = idx >> 6, j = idx & 63;
            size_t base = (size_t)(b49 + kk)*1280 + 512 + j0 + j;
            ck_s[j*49 + kk] = g_ekcat[base];
            pq_s[j*49 + kk] = g_eqcat[base] + bc1[j0 + j];
        }
        __syncthreads();
#pragma unroll 8
        for (int j = 0; j < PTILE; j++) {
            float xc = pq_s[j*49 + qc] + ck_s[j*49 + k];
            s1 += xc; s2 = fmaf(xc, xc, s2);
        }
    }
    float mu = s1 * (1.f/256.f);
    float rs = rsqrtf(s2*(1.f/256.f) - mu*mu + EPSV_);

    float lg[14];
#pragma unroll
    for (int i = 0; i < 14; i++) lg[i] = 0.f;
    for (int jt = 0; jt < 4; jt++) {
        int j0 = jt*PTILE;
        __syncthreads();
        for (int idx = t; idx < PTILE*49; idx += 512) {
            int kk = idx >> 6, j = idx & 63;
            size_t base = (size_t)(b49 + kk)*1280 + 512 + j0 + j;
            ck_s[j*49 + kk] = g_ekcat[base];
            pq_s[j*49 + kk] = g_eqcat[base] + bc1[j0 + j];
        }
        for (int idx = t; idx < PTILE*14; idx += 512) {
            int j = idx / 14, tt = idx - j*14;
            wct_s[j*16 + tt] = Wc2[(size_t)(j0 + j)*14 + tt];
        }
        if (t < PTILE) ab_s[t] = make_float2(gc[j0 + t], bcln[j0 + t]);
        __syncthreads();
#pragma unroll 4
        for (int j = 0; j < PTILE; j++) {
            float xc = pq_s[j*49 + qc] + ck_s[j*49 + k];
            float2 ab = ab_s[j];
            float A = rs * ab.x;
            float y = fmaxf(fmaf(xc, A, ab.y - mu*A), 0.f);
            const float4* w4 = (const float4*)&wct_s[j*16];
            float4 w0 = w4[0], w1 = w4[1], w2v = w4[2], w3v = w4[3];
            lg[0]  = fmaf(y, w0.x,  lg[0]);  lg[1]  = fmaf(y, w0.y,  lg[1]);
            lg[2]  = fmaf(y, w0.z,  lg[2]);  lg[3]  = fmaf(y, w0.w,  lg[3]);
            lg[4]  = fmaf(y, w1.x,  lg[4]);  lg[5]  = fmaf(y, w1.y,  lg[5]);
            lg[6]  = fmaf(y, w1.z,  lg[6]);  lg[7]  = fmaf(y, w1.w,  lg[7]);
            lg[8]  = fmaf(y, w2v.x, lg[8]);  lg[9]  = fmaf(y, w2v.y, lg[9]);
            lg[10] = fmaf(y, w2v.z, lg[10]); lg[11] = fmaf(y, w2v.w, lg[11]);
            lg[12] = fmaf(y, w3v.x, lg[12]); lg[13] = fmaf(y, w3v.y, lg[13]);
        }
    }
    float mx = -1e30f;
#pragma unroll
    for (int tt = 0; tt < 14; tt++) { lg[tt] += s_bc2[tt]; mx = fmaxf(mx, lg[tt]); }
    float se = 0.f, dg = 0.f;
#pragma unroll
    for (int tt = 0; tt < 14; tt++) { float e = expf(lg[tt] - mx); se += e; dg += e*s_reg[tt]; }
    float proj = dg / se * (1.f/(1.f + 1e-8f));

    // ======== relation branch (512 dims, offset 768) ========
    s1 = 0.f; s2 = 0.f;
    for (int jt = 0; jt < 8; jt++) {
        int j0 = jt*PTILE;
        __syncthreads();
        for (int idx = t; idx < PTILE*49; idx += 512) {
            int kk = idx >> 6, j = idx & 63;
            size_t base = (size_t)(b49 + kk)*1280 + 768 + j0 + j;
            ck_s[j*49 + kk] = g_ekcat[base];
            pq_s[j*49 + kk] = g_eqcat[base] + br1[j0 + j];
        }
        __syncthreads();
#pragma unroll 8
        for (int j = 0; j < PTILE; j++) {
            float xr = pq_s[j*49 + qc] + ck_s[j*49 + k];
            s1 += xr; s2 = fmaf(xr, xr, s2);
        }
    }
    float mur = s1 * (1.f/512.f);
    float rsr = rsqrtf(s2*(1.f/512.f) - mur*mur + EPSV_);

    float dr = 0.f;
    for (int jt = 0; jt < 8; jt++) {
        int j0 = jt*PTILE;
        __syncthreads();
        for (int idx = t; idx < PTILE*49; idx += 512) {
            int kk = idx >> 6, j = idx & 63;
            size_t base = (size_t)(b49 + kk)*1280 + 768 + j0 + j;
            ck_s[j*49 + kk] = g_ekcat[base];
            pq_s[j*49 + kk] = g_eqcat[base] + br1[j0 + j];
        }
        if (t < PTILE) {
            ab_s[t] = make_float2(gr[j0 + t], brln[j0 + t]);
            w2_s[t] = g_wr2g[j0 + t];
        }
        __syncthreads();
#pragma unroll 8
        for (int j = 0; j < PTILE; j++) {
            float xr = pq_s[j*49 + qc] + ck_s[j*49 + k];
            float2 ab = ab_s[j];
            float A = rsr * ab.x;
            float y = fmaxf(fmaf(xr, A, ab.y - mur*A), 0.f);
            dr = fmaf(y, w2_s[j], dr);
        }
    }

    if (act) {
        float ga = dr + proj + g_c0[0];
        g_gate[(size_t)(b49 + q)*49 + k] = 1.f/(1.f + expf(-ga));
    }
}

// ---------------- attention per (b,h); also zeroes d_out for atomic gout ----
__global__ void __launch_bounds__(256)
rea_attn(float* __restrict__ out, float* __restrict__ dz) {
    __shared__ float Qt[49*65], Kt[49*65], Vt[49*65];
    __shared__ float wrow[8][52];
    int h = blockIdx.x, b = blockIdx.y;
    int t = threadIdx.x, w = t >> 5, l = t & 31;

    {
        float4 z4 = make_float4(0.f, 0.f, 0.f, 0.f);
        float4* dst = (float4*)dz + (size_t)(b*8 + h)*784;
        for (int i = t; i < 784; i += 256) dst[i] = z4;
    }

    for (int idx = t; idx < 49*64; idx += 256) {
        int q = idx >> 6, d = idx & 63;
        Qt[q*65 + d] = g_eqcat[(size_t)(b*49 + q)*1280 + h*64 + d];
        Kt[q*65 + d] = g_ekcat[(size_t)(b*49 + q)*1280 + h*64 + d];
        Vt[q*65 + d] = g_v[(size_t)(b*49 + q)*512 + h*64 + d];
    }
    __syncthreads();

    for (int q = w; q < 49; q += 8) {
        int m = b*49 + q;
        int k2 = l + 32;
        bool v2 = k2 < 49;
        float g1 = g_gate[(size_t)m*49 + l];
        float g2 = v2 ? g_gate[(size_t)m*49 + k2] : 0.f;
        const float* qr  = Qt + q*65;
        const float* k1r = Kt + l*65;
        const float* k2r = Kt + (v2 ? k2 : l)*65;
        float d1 = 0.f, d2 = 0.f;
#pragma unroll 8
        for (int d = 0; d < 64; d++) {
            float qv = qr[d];
            d1 += qv * k1r[d];
            d2 += qv * k2r[d];
        }
        float lv1 = d1*SCALEV_*(1.f + g1);
        float lv2 = v2 ? d2*SCALEV_*(1.f + g2) : -1e30f;
        float mx = fmaxf(lv1, lv2);
#pragma unroll
        for (int o = 16; o > 0; o >>= 1) mx = fmaxf(mx, __shfl_xor_sync(0xffffffffu, mx, o));
        float e1 = expf(lv1 - mx);
        float e2 = v2 ? expf(lv2 - mx) : 0.f;
        float ssum = wsum(e1 + e2);
        float inv = 1.f / ssum;
        wrow[w][l] = e1 * inv;
        if (v2) wrow[w][k2] = e2 * inv;
        __syncwarp();
        float a1 = 0.f, a2 = 0.f;
        for (int k = 0; k < 49; k++) {
            float wk = wrow[w][k];
            a1 += wk * Vt[k*65 + l];
            a2 += wk * Vt[k*65 + l + 32];
        }
        out[(size_t)m*512 + h*64 + l]      = to_tf32(a1);
        out[(size_t)m*512 + h*64 + l + 32] = to_tf32(a2);
        __syncwarp();
    }
}

// ---------------- launch ----------------
extern "C" void kernel_launch(void* const* d_in, const int* in_sizes, int n_in,
                              void* d_out, int out_size) {
    const float* Q     = (const float*)d_in[0];
    const float* Kin   = (const float*)d_in[1];
    const float* Vin   = (const float*)d_in[2];
    const float* Wq    = (const float*)d_in[3];
    const float* bq    = (const float*)d_in[4];
    const float* Wk    = (const float*)d_in[5];
    const float* bk    = (const float*)d_in[6];
    const float* Wv    = (const float*)d_in[7];
    const float* bv    = (const float*)d_in[8];
    const float* Wo    = (const float*)d_in[9];
    const float* bo    = (const float*)d_in[10];
    const float* rel   = (const float*)d_in[11];
    const float* Wproj = (const float*)d_in[12];
    const float* bproj = (const float*)d_in[13];
    const float* Wgate = (const float*)d_in[14];
    const float* bgate = (const float*)d_in[15];
    const float* Wc1   = (const float*)d_in[16];
    const float* bc1   = (const float*)d_in[17];
    const float* gc    = (const float*)d_in[18];
    const float* bcln  = (const float*)d_in[19];
    const float* Wc2   = (const float*)d_in[20];
    const float* bc2   = (const float*)d_in[21];
    const float* Wr1   = (const float*)d_in[22];
    const float* br1   = (const float*)d_in[23];
    const float* gr    = (const float*)d_in[24];
    const float* brln  = (const float*)d_in[25];
    const float* Wr2   = (const float*)d_in[26];
    const float* br2   = (const float*)d_in[27];
    const float* convW = (const float*)d_in[28];
    const float* convb = (const float*)d_in[29];

    void *p_qr, *p_att, *p_convWt, *p_Wor;
    cudaGetSymbolAddress(&p_qr, g_qr);
    cudaGetSymbolAddress(&p_att, g_att);
    cudaGetSymbolAddress(&p_convWt, g_convWt);
    cudaGetSymbolAddress(&p_Wor, g_Wor);

    static bool attr_set = false;
    if (!attr_set) {
        cudaFuncSetAttribute(rea_gconv, cudaFuncAttributeMaxDynamicSharedMemorySize, GEMM_SMEM);
        cudaFuncSetAttribute(rea_gqkv, cudaFuncAttributeMaxDynamicSharedMemorySize, GEMM_SMEM);
        cudaFuncSetAttribute(rea_gout, cudaFuncAttributeMaxDynamicSharedMemorySize, GEMM_SMEM);
        attr_set = true;
    }

    // 7 launches; ncu captures launch idx 3 => rea_gqkv this round
    rea_prologue<<<3665, 256>>>(convW, Q, Wr2, Wproj, Wgate, rel, br2, bproj, bgate,
                                Wq, Wk, Wc1, Wr1, bq, bk, Wv, Wo);
    rea_gconv<<<dim3(4, 13, 9), 128, GEMM_SMEM>>>((const float*)p_qr,
                                                  (const float*)p_convWt);
    rea_bneqkv<<<296, 256>>>(convb, Q, Kin, Vin);

    rea_gqkv<<<624, 128, GEMM_SMEM>>>(bv);

    rea_pair<<<dim3(32, 5), 512>>>(Wc2, bc1, gc, bcln, bc2, br1, gr, brln);
    rea_attn<<<dim3(8, 32), 256>>>((float*)p_att, (float*)d_out);

    rea_gout<<<dim3(4, 13, 4), 128, GEMM_SMEM>>>((const float*)p_att, (const float*)p_Wor,
                                                 bo, (float*)d_out);
}

// round 11
// speedup vs baseline: 1.0078x; 1.0078x over previous
#include <cuda_runtime.h>
#include <math.h>
#include <stdint.h>

// Problem constants
#define BB_ 32
#define NN_ 49
#define DD_ 512
#define MM_ (BB_*NN_)      // 1568
#define NRELV_ 14
#define EPSV_ 1e-5f
#define SCALEV_ 0.125f     // 1/sqrt(64)

// ---------------- device scratch (no allocations allowed) ----------------
__device__ __align__(256) float g_hconv[MM_*DD_];
__device__ __align__(256) float g_qr[MM_*DD_];
__device__ __align__(256) float g_eq[MM_*DD_];
__device__ __align__(256) float g_ek[MM_*DD_];
__device__ __align__(256) float g_ev[MM_*DD_];
__device__ __align__(256) float g_eqcat[MM_*1280];
__device__ __align__(256) float g_ekcat[MM_*1280];
__device__ __align__(256) float g_v[MM_*DD_];
__device__ __align__(256) float g_att[MM_*DD_];
__device__ __align__(256) float g_convWt[9*512*512];
__device__ __align__(256) float g_Bq[512*1280];
__device__ __align__(256) float g_Bk[512*1280];
__device__ __align__(256) float g_Wvr[512*512];
__device__ __align__(256) float g_Wor[512*512];
__device__ __align__(256) float g_biasq[1280];
__device__ __align__(256) float g_biask[1280];
__device__ float g_sums[1024];
__device__ float g_wr2g[512];
__device__ float g_reg[NRELV_];
__device__ float g_c0[1];
__device__ float g_gate[MM_*NN_];
__device__ unsigned g_bar1 = 0;
__device__ unsigned g_bar2 = 0;

__device__ __forceinline__ float wsum(float v) {
#pragma unroll
    for (int o = 16; o > 0; o >>= 1) v += __shfl_xor_sync(0xffffffffu, v, o);
    return v;
}

__device__ __forceinline__ float to_tf32(float x) {
    uint32_t u;
    asm("cvt.rna.tf32.f32 %0, %1;" : "=r"(u) : "f"(x));
    return __uint_as_float(u);
}

__device__ __forceinline__ void mma_tf32(float* c,
                                         uint32_t a0, uint32_t a1, uint32_t a2, uint32_t a3,
                                         uint32_t b0, uint32_t b1) {
    asm volatile("mma.sync.aligned.m16n8k8.row.col.f32.tf32.tf32.f32 "
                 "{%0,%1,%2,%3}, {%4,%5,%6,%7}, {%8,%9}, {%0,%1,%2,%3};"
                 : "+f"(c[0]), "+f"(c[1]), "+f"(c[2]), "+f"(c[3])
                 : "r"(a0), "r"(a1), "r"(a2), "r"(a3), "r"(b0), "r"(b1));
}

__device__ __forceinline__ void cp16(uint32_t dst, const float* src, bool pred) {
    int sz = pred ? 16 : 0;
    asm volatile("cp.async.cg.shared.global [%0], [%1], 16, %2;\n"
                 :: "r"(dst), "l"(src), "r"(sz));
}
#define CP_COMMIT() asm volatile("cp.async.commit_group;" ::: "memory")
#define CP_WAIT1()  asm volatile("cp.async.wait_group 1;" ::: "memory")

// ---------------- fused prologue: conv repack + Q round/hconv zero + k0 + bcat
__global__ void __launch_bounds__(256)
rea_prologue(const float* __restrict__ convW, const float* __restrict__ Q,
             const float* __restrict__ Wr2, const float* __restrict__ Wproj,
             const float* __restrict__ Wg, const float* __restrict__ rel,
             const float* __restrict__ br2, const float* __restrict__ bproj,
             const float* __restrict__ bgate,
             const float* __restrict__ Wq, const float* __restrict__ Wk,
             const float* __restrict__ Wc1, const float* __restrict__ Wr1,
             const float* __restrict__ bq, const float* __restrict__ bk,
             const float* __restrict__ Wv, const float* __restrict__ Wo) {
    int bx = blockIdx.x, t = threadIdx.x;
    if (bx < 256) {
        __shared__ float ts[32*289];
        int o0 = (bx & 15)*32, c0 = (bx >> 4)*32;
        for (int idx = t; idx < 32*288; idx += 256) {
            int o = idx / 288, r = idx - o*288;   // r = c_local*9 + tap
            ts[o*289 + r] = to_tf32(convW[((size_t)(o0 + o)*512 + c0)*9 + r]);
        }
        __syncthreads();
        for (int idx = t; idx < 288*32; idx += 256) {
            int row = idx >> 5, o = idx & 31;
            int c = row / 9, tap = row - c*9;
            g_convWt[(size_t)tap*262144 + (size_t)(c0 + c)*512 + o0 + o] = ts[o*289 + row];
        }
    } else if (bx < 1040) {
        int idx = (bx - 256)*256 + t;
        if (idx < MM_*DD_/4) {
            float4 qv = ((const float4*)Q)[idx];
            float4 r;
            r.x = to_tf32(qv.x); r.y = to_tf32(qv.y);
            r.z = to_tf32(qv.z); r.w = to_tf32(qv.w);
            ((float4*)g_qr)[idx] = r;
            ((float4*)g_hconv)[idx] = make_float4(0.f, 0.f, 0.f, 0.f);
        }
        if (bx == 256)
            ((float4*)g_sums)[t] = make_float4(0.f, 0.f, 0.f, 0.f);
    } else if (bx < 1105) {
        __shared__ float wg_s[512];
        __shared__ float wpg_s[64];
        int kb = bx - 1040;
        wg_s[t] = Wg[t];
        wg_s[t + 256] = Wg[t + 256];
        __syncthreads();
        int w = t >> 5, l = t & 31;
        if (kb < 64) {
            int row = kb*8 + w;
            float s = 0.f;
            for (int j = l; j < 512; j += 32) s += Wr2[(size_t)row*512 + j] * wg_s[j];
            s = wsum(s);
            if (l == 0) g_wr2g[row] = s;
        } else {
            for (int r = w; r < 64; r += 8) {
                float s = 0.f;
                for (int j = l; j < 512; j += 32) s += Wproj[(size_t)r*512 + j] * wg_s[j];
                s = wsum(s);
                if (l == 0) wpg_s[r] = s;
            }
            __syncthreads();
            if (t < NRELV_) {
                float s = 0.f;
                for (int d = 0; d < 64; d++) s += rel[t*64 + d] * wpg_s[d];
                g_reg[t] = s;
            }
            if (w == 7) {
                float s = 0.f;
                for (int j = l; j < 512; j += 32) s += (br2[j] + bproj[j]) * wg_s[j];
                s = wsum(s);
                if (l == 0) g_c0[0] = s + bgate[0];
            }
        }
    } else {
        int idx = (bx - 1105)*256 + t;
        if (idx < 512*1280) {
            int k = idx / 1280, n = idx - k*1280;
            float vq, vk;
            if (n < 512)       { vq = Wq[(size_t)k*512 + n];              vk = Wk[(size_t)k*512 + n]; }
            else if (n < 768)  { vq = Wc1[(size_t)k*256 + (n-512)];       vk = Wc1[(size_t)(k+512)*256 + (n-512)]; }
            else               { vq = Wr1[(size_t)k*512 + (n-768)];       vk = Wr1[(size_t)(k+512)*512 + (n-768)]; }
            g_Bq[idx] = to_tf32(vq); g_Bk[idx] = to_tf32(vk);
        }
        if (idx < 512*512) {
            g_Wvr[idx] = to_tf32(Wv[idx]);
            g_Wor[idx] = to_tf32(Wo[idx]);
        }
        if (idx < 1280) {
            g_biasq[idx] = idx < 512 ? bq[idx] : 0.f;
            g_biask[idx] = idx < 512 ? bk[idx] : 0.f;
        }
    }
}

// ---------------- TF32 tensor-core GEMM core ----------------
// 128 threads = 4 warps (2M x 2N), warp tile 64x64, block tile 128x128, BK=32,
// 3-stage cp.async ring.
#define BMT 128
#define BNT 128
#define BKT 32
#define APAD 36
#define BPAD 136
#define SZA (BMT*APAD*4)
#define SZB (BKT*BPAD*4)
#define GEMM_SMEM (3*(BMT*APAD + BKT*BPAD)*4)

template <bool CONV, bool ATOMIC>
__device__ __forceinline__ void gemm_core(
    const float* __restrict__ A, const float* __restrict__ Bm,
    const float* __restrict__ bias, float* __restrict__ C,
    int M, int N, int lda, int kbase, int KT, int di, int dj,
    int m0, int n0, int zz,
    float* AsB, float* BsB) {

    int tid = threadIdx.x;
    int lane = tid & 31, warp = tid >> 5;
    int g = lane >> 2, t4 = lane & 3;
    int wm = (warp & 1) * 64, wn = (warp >> 1) * 64;

    uint32_t sA = (uint32_t)__cvta_generic_to_shared(AsB);
    uint32_t sB = (uint32_t)__cvta_generic_to_shared(BsB);

    float acc[4][8][4];
#pragma unroll
    for (int i = 0; i < 4; i++)
#pragma unroll
        for (int j = 0; j < 8; j++)
#pragma unroll
            for (int q = 0; q < 4; q++) acc[i][j][q] = 0.f;

    const float* aptr[8]; bool apred[8]; uint32_t adst[8];
    const float* bptr0; uint32_t bdst0;
#pragma unroll
    for (int h = 0; h < 8; h++) {
        int c = tid + h*128;
        int m = c >> 3, kg = c & 7;
        int gm = m0 + m;
        bool pred;
        const float* p;
        if (!CONV) {
            pred = gm < M;
            p = A + (size_t)(pred ? gm : 0)*lda + kbase + kg*4;
        } else {
            int bb = gm / 49, pos = gm - bb*49;
            int pr = pos / 7, pc = pos - pr*7;
            int ii = pr + di, jj = pc + dj;
            pred = (gm < M) & ((unsigned)ii < 7u) & ((unsigned)jj < 7u);
            p = pred ? (A + ((size_t)(bb*49 + ii*7 + jj))*512 + kg*4) : A;
        }
        apred[h] = pred; aptr[h] = p;
        adst[h] = sA + (uint32_t)(m*APAD + kg*4)*4;
    }
    {
        int kr = tid >> 5, ng = tid & 31;
        bptr0 = Bm + (size_t)(kbase + kr)*N + n0 + ng*4;
        bdst0 = sB + (uint32_t)(kr*BPAD + ng*4)*4;
    }

    auto load_tile = [&](int kt, int buf) {
#pragma unroll
        for (int h = 0; h < 8; h++)
            cp16(adst[h] + buf*SZA, aptr[h] + kt*BKT, apred[h]);
#pragma unroll
        for (int h = 0; h < 8; h++)
            cp16(bdst0 + buf*SZB + (uint32_t)h*4*BPAD*4,
                 bptr0 + (size_t)(kt*BKT + h*4)*N, true);
    };

    load_tile(0, 0); CP_COMMIT();
    if (KT > 1) load_tile(1, 1);
    CP_COMMIT();

    int buf = 0, nbuf = 2;
    for (int kt = 0; kt < KT; kt++) {
        CP_WAIT1();
        __syncthreads();
        if (kt + 2 < KT) load_tile(kt + 2, nbuf);
        CP_COMMIT();
        const float* as = AsB + buf*(BMT*APAD);
        const float* bs = BsB + buf*(BKT*BPAD);
#pragma unroll
        for (int k8 = 0; k8 < 4; k8++) {
            uint32_t af[4][4], bf[8][2];
#pragma unroll
            for (int i = 0; i < 4; i++) {
                int mrow = wm + i*16 + g;
                af[i][0] = __float_as_uint(as[mrow*APAD + k8*8 + t4]);
                af[i][1] = __float_as_uint(as[(mrow + 8)*APAD + k8*8 + t4]);
                af[i][2] = __float_as_uint(as[mrow*APAD + k8*8 + t4 + 4]);
                af[i][3] = __float_as_uint(as[(mrow + 8)*APAD + k8*8 + t4 + 4]);
            }
#pragma unroll
            for (int j = 0; j < 8; j++) {
                int nc = wn + j*8 + g;
                bf[j][0] = __float_as_uint(bs[(k8*8 + t4)*BPAD + nc]);
                bf[j][1] = __float_as_uint(bs[(k8*8 + t4 + 4)*BPAD + nc]);
            }
#pragma unroll
            for (int i = 0; i < 4; i++)
#pragma unroll
                for (int j = 0; j < 8; j++)
                    mma_tf32(acc[i][j], af[i][0], af[i][1], af[i][2], af[i][3],
                             bf[j][0], bf[j][1]);
        }
        buf = (buf == 2) ? 0 : buf + 1;
        nbuf = (nbuf == 2) ? 0 : nbuf + 1;
    }

#pragma unroll
    for (int i = 0; i < 4; i++) {
        int mbase = m0 + wm + i*16 + g;
#pragma unroll
        for (int half = 0; half < 2; half++) {
            int gm = mbase + half*8;
            if (gm < M) {
#pragma unroll
                for (int j = 0; j < 8; j++) {
                    int gn = n0 + wn + j*8 + t4*2;
                    float v0 = acc[i][j][half*2 + 0];
                    float v1 = acc[i][j][half*2 + 1];
                    if (ATOMIC) {
                        if (zz == 0 && bias) { v0 += bias[gn]; v1 += bias[gn + 1]; }
                        atomicAdd(&C[(size_t)gm*N + gn],     v0);
                        atomicAdd(&C[(size_t)gm*N + gn + 1], v1);
                    } else {
                        if (bias) { v0 += bias[gn]; v1 += bias[gn + 1]; }
                        C[(size_t)gm*N + gn]     = v0;
                        C[(size_t)gm*N + gn + 1] = v1;
                    }
                }
            }
        }
    }
}

extern __shared__ float sm_gemm[];

// conv as implicit GEMM, split-K=9 (one tap per z), atomic accumulate into
// pre-zeroed hconv; conv bias added by tap 0.
__global__ void __launch_bounds__(128, 2)
rea_gconv(const float* __restrict__ A, const float* __restrict__ Bm,
          const float* __restrict__ bias) {
    int tap = blockIdx.z;
    gemm_core<true, true>(A, Bm, bias, g_hconv, MM_, 512, 512,
                          tap*512, 16, tap/3 - 1, tap%3 - 1,
                          blockIdx.y*BMT, blockIdx.x*BNT, tap,
                          sm_gemm, sm_gemm + 3*BMT*APAD);
}

// batched eq/ek/ev projections, flat 312-block grid, plain stores
__global__ void __launch_bounds__(128, 2)
rea_gqkv(const float* __restrict__ bv) {
    int bx = blockIdx.x;
    int z, lx;
    if (bx < 130)      { z = 0; lx = bx; }
    else if (bx < 260) { z = 1; lx = bx - 130; }
    else               { z = 2; lx = bx - 260; }
    int m0, n0;
    if (z < 2) { n0 = (lx % 10)*BNT; m0 = (lx / 10)*BMT; }
    else       { n0 = (lx & 3)*BNT;  m0 = (lx >> 2)*BMT; }
    const float* A    = z == 0 ? g_eq    : z == 1 ? g_ek    : g_ev;
    const float* Bm   = z == 0 ? g_Bq    : z == 1 ? g_Bk    : g_Wvr;
    const float* bias = z == 0 ? g_biasq : z == 1 ? g_biask : bv;
    float*       C    = z == 0 ? g_eqcat : z == 1 ? g_ekcat : g_v;
    int N = z < 2 ? 1280 : 512;
    gemm_core<false, false>(A, Bm, bias, C, MM_, N, 512, 0, 16, 0, 0,
                            m0, n0, 0, sm_gemm, sm_gemm + 3*BMT*APAD);
}

// output projection, split-K=4, atomic into pre-zeroed d_out
__global__ void __launch_bounds__(128, 2)
rea_gout(const float* __restrict__ A, const float* __restrict__ Bm,
         const float* __restrict__ bias, float* __restrict__ C) {
    gemm_core<false, true>(A, Bm, bias, C, MM_, 512, 512,
                           blockIdx.z*128, 4, 0, 0,
                           blockIdx.y*BMT, blockIdx.x*BNT, blockIdx.z,
                           sm_gemm, sm_gemm + 3*BMT*APAD);
}

// ---------------- fused: BN stats from hconv | barrier | eqkv ----------------
// 296 blocks x 256 threads, all resident (no smem, low regs); spin barrier
// with self-resetting counters (graph-replay safe).
__global__ void __launch_bounds__(256)
rea_bneqkv(const float* __restrict__ Q,
           const float* __restrict__ Kin, const float* __restrict__ Vin) {
    int t = threadIdx.x;
    // ---- phase A: BN stats over hconv ----
    for (int gb = blockIdx.x; gb < 98; gb += 296) {
        int c4 = t & 127;
        int rh = t >> 7;
        int r0 = gb*16;
        float4 s1 = make_float4(0.f, 0.f, 0.f, 0.f);
        float4 s2 = make_float4(0.f, 0.f, 0.f, 0.f);
#pragma unroll
        for (int it = 0; it < 8; it++) {
            int r = r0 + it*2 + rh;
            float4 a = ((const float4*)g_hconv)[(size_t)r*128 + c4];
            s1.x += a.x; s1.y += a.y; s1.z += a.z; s1.w += a.w;
            s2.x = fmaf(a.x, a.x, s2.x); s2.y = fmaf(a.y, a.y, s2.y);
            s2.z = fmaf(a.z, a.z, s2.z); s2.w = fmaf(a.w, a.w, s2.w);
        }
        int c = c4*4;
        atomicAdd(&g_sums[c + 0], s1.x); atomicAdd(&g_sums[c + 1], s1.y);
        atomicAdd(&g_sums[c + 2], s1.z); atomicAdd(&g_sums[c + 3], s1.w);
        atomicAdd(&g_sums[512 + c + 0], s2.x); atomicAdd(&g_sums[512 + c + 1], s2.y);
        atomicAdd(&g_sums[512 + c + 2], s2.z); atomicAdd(&g_sums[512 + c + 3], s2.w);
    }
    // ---- device-wide barrier ----
    __syncthreads();
    __threadfence();
    if (t == 0) {
        atomicAdd(&g_bar1, 1u);
        while (atomicAdd(&g_bar1, 0u) < 296u) { }
    }
    __syncthreads();
    // ---- phase B: eqkv ----
    int gstep = 296*256;
    for (int idx = blockIdx.x*256 + t; idx < MM_*DD_/4; idx += gstep) {
        int c = (idx*4) & 511;
        float4 sm = *(const float4*)&g_sums[c];
        float4 sq = *(const float4*)&g_sums[512 + c];
        float4 hv = ((const float4*)g_hconv)[idx];
        float4 qv = ((const float4*)Q)[idx];
        float4 kv = ((const float4*)Kin)[idx];
        float4 vv = ((const float4*)Vin)[idx];
        float4 eq, ek, ev;
#define BN1(comp) { \
        float mu = sm.comp * (1.f/1568.f); \
        float var = sq.comp * (1.f/1568.f) - mu*mu; \
        float xn = fmaxf((hv.comp - mu) * rsqrtf(var + EPSV_), 0.f); \
        eq.comp = to_tf32(xn + qv.comp); \
        ek.comp = to_tf32(xn + kv.comp); \
        ev.comp = to_tf32(xn + vv.comp); }
        BN1(x) BN1(y) BN1(z) BN1(w)
#undef BN1
        ((float4*)g_eq)[idx] = eq;
        ((float4*)g_ek)[idx] = ek;
        ((float4*)g_ev)[idx] = ev;
    }
    // ---- reset barrier counters for next graph replay ----
    __syncthreads();
    if (t == 0) {
        unsigned v = atomicAdd(&g_bar2, 1u);
        if (v == 295u) { g_bar1 = 0u; g_bar2 = 0u; __threadfence(); }
    }
}

// ---------------- per-pair gate: one pair per LANE, j-dim tiled in smem ------
#define PTILE 64
__global__ void __launch_bounds__(512)
rea_pair(const float* __restrict__ Wc2, const float* __restrict__ bc1,
         const float* __restrict__ gc, const float* __restrict__ bcln,
         const float* __restrict__ bc2, const float* __restrict__ br1,
         const float* __restrict__ gr, const float* __restrict__ brln) {
    __shared__ float ck_s[PTILE*49];
    __shared__ float pq_s[PTILE*49];
    __shared__ float wct_s[PTILE*16];
    __shared__ float2 ab_s[PTILE];
    __shared__ float w2_s[PTILE];
    __shared__ float s_bc2[16], s_reg[16];

    int b = blockIdx.x;
    int t = threadIdx.x;
    int p = blockIdx.y*512 + t;
    int q = p / 49, k = p - q*49;
    bool act = q < 49;
    int qc = act ? q : 48;
    int b49 = b*49;

    if (t < NRELV_) { s_bc2[t] = bc2[t]; s_reg[t] = g_reg[t]; }
    if (t < PTILE) { wct_s[t*16 + 14] = 0.f; wct_s[t*16 + 15] = 0.f; }

    // ======== channel branch (256 dims, offset 512) ========
    float s1 = 0.f, s2 = 0.f;
    for (int jt = 0; jt < 4; jt++) {
        int j0 = jt*PTILE;
        __syncthreads();
        for (int idx = t; idx < PTILE*49; idx += 512) {
            int kk = idx >> 6, j = idx & 63;
            size_t base = (size_t)(b49 + kk)*1280 + 512 + j0 + j;
            ck_s[j*49 + kk] = g_ekcat[base];
            pq_s[j*49 + kk] = g_eqcat[base] + bc1[j0 + j];
        }
        __syncthreads();
#pragma unroll 8
        for (int j = 0; j < PTILE; j++) {
            float xc = pq_s[j*49 + qc] + ck_s[j*49 + k];
            s1 += xc; s2 = fmaf(xc, xc, s2);
        }
    }
    float mu = s1 * (1.f/256.f);
    float rs = rsqrtf(s2*(1.f/256.f) - mu*mu + EPSV_);

    float lg[14];
#pragma unroll
    for (int i = 0; i < 14; i++) lg[i] = 0.f;
    for (int jt = 0; jt < 4; jt++) {
        int j0 = jt*PTILE;
        __syncthreads();
        for (int idx = t; idx < PTILE*49; idx += 512) {
            int kk = idx >> 6, j = idx & 63;
            size_t base = (size_t)(b49 + kk)*1280 + 512 + j0 + j;
            ck_s[j*49 + kk] = g_ekcat[base];
            pq_s[j*49 + kk] = g_eqcat[base] + bc1[j0 + j];
        }
        for (int idx = t; idx < PTILE*14; idx += 512) {
            int j = idx / 14, tt = idx - j*14;
            wct_s[j*16 + tt] = Wc2[(size_t)(j0 + j)*14 + tt];
        }
        if (t < PTILE) ab_s[t] = make_float2(gc[j0 + t], bcln[j0 + t]);
        __syncthreads();
#pragma unroll 4
        for (int j = 0; j < PTILE; j++) {
            float xc = pq_s[j*49 + qc] + ck_s[j*49 + k];
            float2 ab = ab_s[j];
            float A = rs * ab.x;
            float y = fmaxf(fmaf(xc, A, ab.y - mu*A), 0.f);
            const float4* w4 = (const float4*)&wct_s[j*16];
            float4 w0 = w4[0], w1 = w4[1], w2v = w4[2], w3v = w4[3];
            lg[0]  = fmaf(y, w0.x,  lg[0]);  lg[1]  = fmaf(y, w0.y,  lg[1]);
            lg[2]  = fmaf(y, w0.z,  lg[2]);  lg[3]  = fmaf(y, w0.w,  lg[3]);
            lg[4]  = fmaf(y, w1.x,  lg[4]);  lg[5]  = fmaf(y, w1.y,  lg[5]);
            lg[6]  = fmaf(y, w1.z,  lg[6]);  lg[7]  = fmaf(y, w1.w,  lg[7]);
            lg[8]  = fmaf(y, w2v.x, lg[8]);  lg[9]  = fmaf(y, w2v.y, lg[9]);
            lg[10] = fmaf(y, w2v.z, lg[10]); lg[11] = fmaf(y, w2v.w, lg[11]);
            lg[12] = fmaf(y, w3v.x, lg[12]); lg[13] = fmaf(y, w3v.y, lg[13]);
        }
    }
    float mx = -1e30f;
#pragma unroll
    for (int tt = 0; tt < 14; tt++) { lg[tt] += s_bc2[tt]; mx = fmaxf(mx, lg[tt]); }
    float se = 0.f, dg = 0.f;
#pragma unroll
    for (int tt = 0; tt < 14; tt++) { float e = expf(lg[tt] - mx); se += e; dg += e*s_reg[tt]; }
    float proj = dg / se * (1.f/(1.f + 1e-8f));

    // ======== relation branch (512 dims, offset 768) ========
    s1 = 0.f; s2 = 0.f;
    for (int jt = 0; jt < 8; jt++) {
        int j0 = jt*PTILE;
        __syncthreads();
        for (int idx = t; idx < PTILE*49; idx += 512) {
            int kk = idx >> 6, j = idx & 63;
            size_t base = (size_t)(b49 + kk)*1280 + 768 + j0 + j;
            ck_s[j*49 + kk] = g_ekcat[base];
            pq_s[j*49 + kk] = g_eqcat[base] + br1[j0 + j];
        }
        __syncthreads();
#pragma unroll 8
        for (int j = 0; j < PTILE; j++) {
            float xr = pq_s[j*49 + qc] + ck_s[j*49 + k];
            s1 += xr; s2 = fmaf(xr, xr, s2);
        }
    }
    float mur = s1 * (1.f/512.f);
    float rsr = rsqrtf(s2*(1.f/512.f) - mur*mur + EPSV_);

    float dr = 0.f;
    for (int jt = 0; jt < 8; jt++) {
        int j0 = jt*PTILE;
        __syncthreads();
        for (int idx = t; idx < PTILE*49; idx += 512) {
            int kk = idx >> 6, j = idx & 63;
            size_t base = (size_t)(b49 + kk)*1280 + 768 + j0 + j;
            ck_s[j*49 + kk] = g_ekcat[base];
            pq_s[j*49 + kk] = g_eqcat[base] + br1[j0 + j];
        }
        if (t < PTILE) {
            ab_s[t] = make_float2(gr[j0 + t], brln[j0 + t]);
            w2_s[t] = g_wr2g[j0 + t];
        }
        __syncthreads();
#pragma unroll 8
        for (int j = 0; j < PTILE; j++) {
            float xr = pq_s[j*49 + qc] + ck_s[j*49 + k];
            float2 ab = ab_s[j];
            float A = rsr * ab.x;
            float y = fmaxf(fmaf(xr, A, ab.y - mur*A), 0.f);
            dr = fmaf(y, w2_s[j], dr);
        }
    }

    if (act) {
        float ga = dr + proj + g_c0[0];
        g_gate[(size_t)(b49 + q)*49 + k] = 1.f/(1.f + expf(-ga));
    }
}

// ---------------- attention per (b,h); also zeroes d_out for atomic gout ----
__global__ void __launch_bounds__(256)
rea_attn(float* __restrict__ out, float* __restrict__ dz) {
    __shared__ float Qt[49*65], Kt[49*65], Vt[49*65];
    __shared__ float wrow[8][52];
    int h = blockIdx.x, b = blockIdx.y;
    int t = threadIdx.x, w = t >> 5, l = t & 31;

    {
        float4 z4 = make_float4(0.f, 0.f, 0.f, 0.f);
        float4* dst = (float4*)dz + (size_t)(b*8 + h)*784;
        for (int i = t; i < 784; i += 256) dst[i] = z4;
    }

    for (int idx = t; idx < 49*64; idx += 256) {
        int q = idx >> 6, d = idx & 63;
        Qt[q*65 + d] = g_eqcat[(size_t)(b*49 + q)*1280 + h*64 + d];
        Kt[q*65 + d] = g_ekcat[(size_t)(b*49 + q)*1280 + h*64 + d];
        Vt[q*65 + d] = g_v[(size_t)(b*49 + q)*512 + h*64 + d];
    }
    __syncthreads();

    for (int q = w; q < 49; q += 8) {
        int m = b*49 + q;
        int k2 = l + 32;
        bool v2 = k2 < 49;
        float g1 = g_gate[(size_t)m*49 + l];
        float g2 = v2 ? g_gate[(size_t)m*49 + k2] : 0.f;
        const float* qr  = Qt + q*65;
        const float* k1r = Kt + l*65;
        const float* k2r = Kt + (v2 ? k2 : l)*65;
        float d1 = 0.f, d2 = 0.f;
#pragma unroll 8
        for (int d = 0; d < 64; d++) {
            float qv = qr[d];
            d1 += qv * k1r[d];
            d2 += qv * k2r[d];
        }
        float lv1 = d1*SCALEV_*(1.f + g1);
        float lv2 = v2 ? d2*SCALEV_*(1.f + g2) : -1e30f;
        float mx = fmaxf(lv1, lv2);
#pragma unroll
        for (int o = 16; o > 0; o >>= 1) mx = fmaxf(mx, __shfl_xor_sync(0xffffffffu, mx, o));
        float e1 = expf(lv1 - mx);
        float e2 = v2 ? expf(lv2 - mx) : 0.f;
        float ssum = wsum(e1 + e2);
        float inv = 1.f / ssum;
        wrow[w][l] = e1 * inv;
        if (v2) wrow[w][k2] = e2 * inv;
        __syncwarp();
        float a1 = 0.f, a2 = 0.f;
        for (int k = 0; k < 49; k++) {
            float wk = wrow[w][k];
            a1 += wk * Vt[k*65 + l];
            a2 += wk * Vt[k*65 + l + 32];
        }
        out[(size_t)m*512 + h*64 + l]      = to_tf32(a1);
        out[(size_t)m*512 + h*64 + l + 32] = to_tf32(a2);
        __syncwarp();
    }
}

// ---------------- launch ----------------
extern "C" void kernel_launch(void* const* d_in, const int* in_sizes, int n_in,
                              void* d_out, int out_size) {
    const float* Q     = (const float*)d_in[0];
    const float* Kin   = (const float*)d_in[1];
    const float* Vin   = (const float*)d_in[2];
    const float* Wq    = (const float*)d_in[3];
    const float* bq    = (const float*)d_in[4];
    const float* Wk    = (const float*)d_in[5];
    const float* bk    = (const float*)d_in[6];
    const float* Wv    = (const float*)d_in[7];
    const float* bv    = (const float*)d_in[8];
    const float* Wo    = (const float*)d_in[9];
    const float* bo    = (const float*)d_in[10];
    const float* rel   = (const float*)d_in[11];
    const float* Wproj = (const float*)d_in[12];
    const float* bproj = (const float*)d_in[13];
    const float* Wgate = (const float*)d_in[14];
    const float* bgate = (const float*)d_in[15];
    const float* Wc1   = (const float*)d_in[16];
    const float* bc1   = (const float*)d_in[17];
    const float* gc    = (const float*)d_in[18];
    const float* bcln  = (const float*)d_in[19];
    const float* Wc2   = (const float*)d_in[20];
    const float* bc2   = (const float*)d_in[21];
    const float* Wr1   = (const float*)d_in[22];
    const float* br1   = (const float*)d_in[23];
    const float* gr    = (const float*)d_in[24];
    const float* brln  = (const float*)d_in[25];
    const float* Wr2   = (const float*)d_in[26];
    const float* br2   = (const float*)d_in[27];
    const float* convW = (const float*)d_in[28];
    const float* convb = (const float*)d_in[29];

    void *p_qr, *p_att, *p_convWt, *p_Wor;
    cudaGetSymbolAddress(&p_qr, g_qr);
    cudaGetSymbolAddress(&p_att, g_att);
    cudaGetSymbolAddress(&p_convWt, g_convWt);
    cudaGetSymbolAddress(&p_Wor, g_Wor);

    static bool attr_set = false;
    if (!attr_set) {
        cudaFuncSetAttribute(rea_gconv, cudaFuncAttributeMaxDynamicSharedMemorySize, GEMM_SMEM);
        cudaFuncSetAttribute(rea_gqkv, cudaFuncAttributeMaxDynamicSharedMemorySize, GEMM_SMEM);
        cudaFuncSetAttribute(rea_gout, cudaFuncAttributeMaxDynamicSharedMemorySize, GEMM_SMEM);
        attr_set = true;
    }

    // 7 launches; ncu captures launch idx 3 => rea_gqkv (non-atomic variant)
    rea_prologue<<<3665, 256>>>(convW, Q, Wr2, Wproj, Wgate, rel, br2, bproj, bgate,
                                Wq, Wk, Wc1, Wr1, bq, bk, Wv, Wo);
    rea_gconv<<<dim3(4, 13, 9), 128, GEMM_SMEM>>>((const float*)p_qr,
                                                  (const float*)p_convWt, convb);
    rea_bneqkv<<<296, 256>>>(Q, Kin, Vin);

    rea_gqkv<<<312, 128, GEMM_SMEM>>>(bv);

    rea_pair<<<dim3(32, 5), 512>>>(Wc2, bc1, gc, bcln, bc2, br1, gr, brln);
    rea_attn<<<dim3(8, 32), 256>>>((float*)p_att, (float*)d_out);

    rea_gout<<<dim3(4, 13, 4), 128, GEMM_SMEM>>>((const float*)p_att, (const float*)p_Wor,
                                                 bo, (float*)d_out);
}

// round 12
// speedup vs baseline: 1.0600x; 1.0519x over previous
#include <cuda_runtime.h>
#include <math.h>
#include <stdint.h>

// Problem constants
#define BB_ 32
#define NN_ 49
#define DD_ 512
#define MM_ (BB_*NN_)      // 1568
#define NRELV_ 14
#define EPSV_ 1e-5f
#define SCALEV_ 0.125f     // 1/sqrt(64)

typedef unsigned long long ull;

// ---------------- device scratch (no allocations allowed) ----------------
__device__ __align__(256) float g_hconv[MM_*DD_];
__device__ __align__(256) float g_qr[MM_*DD_];
__device__ __align__(256) float g_eq[MM_*DD_];
__device__ __align__(256) float g_ek[MM_*DD_];
__device__ __align__(256) float g_ev[MM_*DD_];
__device__ __align__(256) float g_eqcat[MM_*1280];
__device__ __align__(256) float g_ekcat[MM_*1280];
__device__ __align__(256) float g_v[MM_*DD_];
__device__ __align__(256) float g_att[MM_*DD_];
__device__ __align__(256) float g_convWt[9*512*512];
__device__ __align__(256) float g_Bq[512*1280];
__device__ __align__(256) float g_Bk[512*1280];
__device__ __align__(256) float g_Wvr[512*512];
__device__ __align__(256) float g_Wor[512*512];
__device__ __align__(256) float g_biasq[1280];
__device__ __align__(256) float g_biask[1280];
__device__ float g_sums[1024];
__device__ float g_wr2g[512];
__device__ float g_reg[NRELV_];
__device__ float g_c0[1];
__device__ float g_gate[MM_*NN_];
__device__ unsigned g_bar1 = 0;
__device__ unsigned g_bar2 = 0;
__device__ unsigned g_bar3 = 0;

__device__ __forceinline__ float wsum(float v) {
#pragma unroll
    for (int o = 16; o > 0; o >>= 1) v += __shfl_xor_sync(0xffffffffu, v, o);
    return v;
}

__device__ __forceinline__ float to_tf32(float x) {
    uint32_t u;
    asm("cvt.rna.tf32.f32 %0, %1;" : "=r"(u) : "f"(x));
    return __uint_as_float(u);
}

__device__ __forceinline__ void mma_tf32(float* c,
                                         uint32_t a0, uint32_t a1, uint32_t a2, uint32_t a3,
                                         uint32_t b0, uint32_t b1) {
    asm volatile("mma.sync.aligned.m16n8k8.row.col.f32.tf32.tf32.f32 "
                 "{%0,%1,%2,%3}, {%4,%5,%6,%7}, {%8,%9}, {%0,%1,%2,%3};"
                 : "+f"(c[0]), "+f"(c[1]), "+f"(c[2]), "+f"(c[3])
                 : "r"(a0), "r"(a1), "r"(a2), "r"(a3), "r"(b0), "r"(b1));
}

__device__ __forceinline__ void cp16(uint32_t dst, const float* src, bool pred) {
    int sz = pred ? 16 : 0;
    asm volatile("cp.async.cg.shared.global [%0], [%1], 16, %2;\n"
                 :: "r"(dst), "l"(src), "r"(sz));
}
#define CP_COMMIT() asm volatile("cp.async.commit_group;" ::: "memory")
#define CP_WAIT1()  asm volatile("cp.async.wait_group 1;" ::: "memory")

// packed f32x2 helpers (sm_103a FFMA2)
__device__ __forceinline__ ull pk2(float a, float b) {
    ull r; asm("mov.b64 %0, {%1, %2};" : "=l"(r) : "f"(a), "f"(b)); return r;
}
__device__ __forceinline__ void upk2(ull v, float& a, float& b) {
    asm("mov.b64 {%0, %1}, %2;" : "=f"(a), "=f"(b) : "l"(v));
}
__device__ __forceinline__ ull fma2v(ull a, ull b, ull c) {
    ull d; asm("fma.rn.f32x2 %0, %1, %2, %3;" : "=l"(d) : "l"(a), "l"(b), "l"(c));
    return d;
}

// ---------------- fused prologue: conv repack + Q round/hconv zero + k0 + bcat
__global__ void __launch_bounds__(256)
rea_prologue(const float* __restrict__ convW, const float* __restrict__ Q,
             const float* __restrict__ Wr2, const float* __restrict__ Wproj,
             const float* __restrict__ Wg, const float* __restrict__ rel,
             const float* __restrict__ br2, const float* __restrict__ bproj,
             const float* __restrict__ bgate,
             const float* __restrict__ Wq, const float* __restrict__ Wk,
             const float* __restrict__ Wc1, const float* __restrict__ Wr1,
             const float* __restrict__ bq, const float* __restrict__ bk,
             const float* __restrict__ Wv, const float* __restrict__ Wo) {
    int bx = blockIdx.x, t = threadIdx.x;
    if (bx < 256) {
        __shared__ float ts[32*289];
        int o0 = (bx & 15)*32, c0 = (bx >> 4)*32;
        for (int idx = t; idx < 32*288; idx += 256) {
            int o = idx / 288, r = idx - o*288;   // r = c_local*9 + tap
            ts[o*289 + r] = to_tf32(convW[((size_t)(o0 + o)*512 + c0)*9 + r]);
        }
        __syncthreads();
        for (int idx = t; idx < 288*32; idx += 256) {
            int row = idx >> 5, o = idx & 31;
            int c = row / 9, tap = row - c*9;
            g_convWt[(size_t)tap*262144 + (size_t)(c0 + c)*512 + o0 + o] = ts[o*289 + row];
        }
    } else if (bx < 1040) {
        int idx = (bx - 256)*256 + t;
        if (idx < MM_*DD_/4) {
            float4 qv = ((const float4*)Q)[idx];
            float4 r;
            r.x = to_tf32(qv.x); r.y = to_tf32(qv.y);
            r.z = to_tf32(qv.z); r.w = to_tf32(qv.w);
            ((float4*)g_qr)[idx] = r;
            ((float4*)g_hconv)[idx] = make_float4(0.f, 0.f, 0.f, 0.f);
        }
        if (bx == 256)
            ((float4*)g_sums)[t] = make_float4(0.f, 0.f, 0.f, 0.f);
    } else if (bx < 1105) {
        __shared__ float wg_s[512];
        __shared__ float wpg_s[64];
        int kb = bx - 1040;
        wg_s[t] = Wg[t];
        wg_s[t + 256] = Wg[t + 256];
        __syncthreads();
        int w = t >> 5, l = t & 31;
        if (kb < 64) {
            int row = kb*8 + w;
            float s = 0.f;
            for (int j = l; j < 512; j += 32) s += Wr2[(size_t)row*512 + j] * wg_s[j];
            s = wsum(s);
            if (l == 0) g_wr2g[row] = s;
        } else {
            for (int r = w; r < 64; r += 8) {
                float s = 0.f;
                for (int j = l; j < 512; j += 32) s += Wproj[(size_t)r*512 + j] * wg_s[j];
                s = wsum(s);
                if (l == 0) wpg_s[r] = s;
            }
            __syncthreads();
            if (t < NRELV_) {
                float s = 0.f;
                for (int d = 0; d < 64; d++) s += rel[t*64 + d] * wpg_s[d];
                g_reg[t] = s;
            }
            if (w == 7) {
                float s = 0.f;
                for (int j = l; j < 512; j += 32) s += (br2[j] + bproj[j]) * wg_s[j];
                s = wsum(s);
                if (l == 0) g_c0[0] = s + bgate[0];
            }
        }
    } else {
        int idx = (bx - 1105)*256 + t;
        if (idx < 512*1280) {
            int k = idx / 1280, n = idx - k*1280;
            float vq, vk;
            if (n < 512)       { vq = Wq[(size_t)k*512 + n];              vk = Wk[(size_t)k*512 + n]; }
            else if (n < 768)  { vq = Wc1[(size_t)k*256 + (n-512)];       vk = Wc1[(size_t)(k+512)*256 + (n-512)]; }
            else               { vq = Wr1[(size_t)k*512 + (n-768)];       vk = Wr1[(size_t)(k+512)*512 + (n-768)]; }
            g_Bq[idx] = to_tf32(vq); g_Bk[idx] = to_tf32(vk);
        }
        if (idx < 512*512) {
            g_Wvr[idx] = to_tf32(Wv[idx]);
            g_Wor[idx] = to_tf32(Wo[idx]);
        }
        if (idx < 1280) {
            g_biasq[idx] = idx < 512 ? bq[idx] : 0.f;
            g_biask[idx] = idx < 512 ? bk[idx] : 0.f;
        }
    }
}

// ---------------- TF32 tensor-core GEMM core ----------------
#define BMT 128
#define BNT 128
#define BKT 32
#define APAD 36
#define BPAD 136
#define SZA (BMT*APAD*4)
#define SZB (BKT*BPAD*4)
#define GEMM_SMEM (3*(BMT*APAD + BKT*BPAD)*4)

template <bool CONV, bool ATOMIC>
__device__ __forceinline__ void gemm_core(
    const float* __restrict__ A, const float* __restrict__ Bm,
    const float* __restrict__ bias, float* __restrict__ C,
    int M, int N, int lda, int kbase, int KT, int di, int dj,
    int m0, int n0, int zz,
    float* AsB, float* BsB) {

    int tid = threadIdx.x;
    int lane = tid & 31, warp = tid >> 5;
    int g = lane >> 2, t4 = lane & 3;
    int wm = (warp & 1) * 64, wn = (warp >> 1) * 64;

    uint32_t sA = (uint32_t)__cvta_generic_to_shared(AsB);
    uint32_t sB = (uint32_t)__cvta_generic_to_shared(BsB);

    float acc[4][8][4];
#pragma unroll
    for (int i = 0; i < 4; i++)
#pragma unroll
        for (int j = 0; j < 8; j++)
#pragma unroll
            for (int q = 0; q < 4; q++) acc[i][j][q] = 0.f;

    const float* aptr[8]; bool apred[8]; uint32_t adst[8];
    const float* bptr0; uint32_t bdst0;
#pragma unroll
    for (int h = 0; h < 8; h++) {
        int c = tid + h*128;
        int m = c >> 3, kg = c & 7;
        int gm = m0 + m;
        bool pred;
        const float* p;
        if (!CONV) {
            pred = gm < M;
            p = A + (size_t)(pred ? gm : 0)*lda + kbase + kg*4;
        } else {
            int bb = gm / 49, pos = gm - bb*49;
            int pr = pos / 7, pc = pos - pr*7;
            int ii = pr + di, jj = pc + dj;
            pred = (gm < M) & ((unsigned)ii < 7u) & ((unsigned)jj < 7u);
            p = pred ? (A + ((size_t)(bb*49 + ii*7 + jj))*512 + kg*4) : A;
        }
        apred[h] = pred; aptr[h] = p;
        adst[h] = sA + (uint32_t)(m*APAD + kg*4)*4;
    }
    {
        int kr = tid >> 5, ng = tid & 31;
        bptr0 = Bm + (size_t)(kbase + kr)*N + n0 + ng*4;
        bdst0 = sB + (uint32_t)(kr*BPAD + ng*4)*4;
    }

    auto load_tile = [&](int kt, int buf) {
#pragma unroll
        for (int h = 0; h < 8; h++)
            cp16(adst[h] + buf*SZA, aptr[h] + kt*BKT, apred[h]);
#pragma unroll
        for (int h = 0; h < 8; h++)
            cp16(bdst0 + buf*SZB + (uint32_t)h*4*BPAD*4,
                 bptr0 + (size_t)(kt*BKT + h*4)*N, true);
    };

    load_tile(0, 0); CP_COMMIT();
    if (KT > 1) load_tile(1, 1);
    CP_COMMIT();

    int buf = 0, nbuf = 2;
    for (int kt = 0; kt < KT; kt++) {
        CP_WAIT1();
        __syncthreads();
        if (kt + 2 < KT) load_tile(kt + 2, nbuf);
        CP_COMMIT();
        const float* as = AsB + buf*(BMT*APAD);
        const float* bs = BsB + buf*(BKT*BPAD);
#pragma unroll
        for (int k8 = 0; k8 < 4; k8++) {
            uint32_t af[4][4], bf[8][2];
#pragma unroll
            for (int i = 0; i < 4; i++) {
                int mrow = wm + i*16 + g;
                af[i][0] = __float_as_uint(as[mrow*APAD + k8*8 + t4]);
                af[i][1] = __float_as_uint(as[(mrow + 8)*APAD + k8*8 + t4]);
                af[i][2] = __float_as_uint(as[mrow*APAD + k8*8 + t4 + 4]);
                af[i][3] = __float_as_uint(as[(mrow + 8)*APAD + k8*8 + t4 + 4]);
            }
#pragma unroll
            for (int j = 0; j < 8; j++) {
                int nc = wn + j*8 + g;
                bf[j][0] = __float_as_uint(bs[(k8*8 + t4)*BPAD + nc]);
                bf[j][1] = __float_as_uint(bs[(k8*8 + t4 + 4)*BPAD + nc]);
            }
#pragma unroll
            for (int i = 0; i < 4; i++)
#pragma unroll
                for (int j = 0; j < 8; j++)
                    mma_tf32(acc[i][j], af[i][0], af[i][1], af[i][2], af[i][3],
                             bf[j][0], bf[j][1]);
        }
        buf = (buf == 2) ? 0 : buf + 1;
        nbuf = (nbuf == 2) ? 0 : nbuf + 1;
    }

#pragma unroll
    for (int i = 0; i < 4; i++) {
        int mbase = m0 + wm + i*16 + g;
#pragma unroll
        for (int half = 0; half < 2; half++) {
            int gm = mbase + half*8;
            if (gm < M) {
#pragma unroll
                for (int j = 0; j < 8; j++) {
                    int gn = n0 + wn + j*8 + t4*2;
                    float v0 = acc[i][j][half*2 + 0];
                    float v1 = acc[i][j][half*2 + 1];
                    if (ATOMIC) {
                        if (zz == 0 && bias) { v0 += bias[gn]; v1 += bias[gn + 1]; }
                        atomicAdd(&C[(size_t)gm*N + gn],     v0);
                        atomicAdd(&C[(size_t)gm*N + gn + 1], v1);
                    } else {
                        if (bias) { v0 += bias[gn]; v1 += bias[gn + 1]; }
                        C[(size_t)gm*N + gn]     = v0;
                        C[(size_t)gm*N + gn + 1] = v1;
                    }
                }
            }
        }
    }
}

extern __shared__ float sm_gemm[];

// conv as implicit GEMM, split-K=9, atomic accumulate into pre-zeroed hconv
__global__ void __launch_bounds__(128, 2)
rea_gconv(const float* __restrict__ A, const float* __restrict__ Bm,
          const float* __restrict__ bias) {
    int tap = blockIdx.z;
    gemm_core<true, true>(A, Bm, bias, g_hconv, MM_, 512, 512,
                          tap*512, 16, tap/3 - 1, tap%3 - 1,
                          blockIdx.y*BMT, blockIdx.x*BNT, tap,
                          sm_gemm, sm_gemm + 3*BMT*APAD);
}

// fused: BN stats | bar | eqkv | bar | eq/ek/ev projections (296 blocks resident)
__global__ void __launch_bounds__(128, 2)
rea_gqkv(const float* __restrict__ bv, const float* __restrict__ Q,
         const float* __restrict__ Kin, const float* __restrict__ Vin) {
    int bx = blockIdx.x, t = threadIdx.x;
    // ---- phase A: BN stats from hconv ----
    if (bx < 98) {
        float4 s1 = make_float4(0.f, 0.f, 0.f, 0.f);
        float4 s2 = make_float4(0.f, 0.f, 0.f, 0.f);
#pragma unroll
        for (int it = 0; it < 16; it++) {
            float4 a = ((const float4*)g_hconv)[(size_t)(bx*16 + it)*128 + t];
            s1.x += a.x; s1.y += a.y; s1.z += a.z; s1.w += a.w;
            s2.x = fmaf(a.x, a.x, s2.x); s2.y = fmaf(a.y, a.y, s2.y);
            s2.z = fmaf(a.z, a.z, s2.z); s2.w = fmaf(a.w, a.w, s2.w);
        }
        int c = t*4;
        atomicAdd(&g_sums[c + 0], s1.x); atomicAdd(&g_sums[c + 1], s1.y);
        atomicAdd(&g_sums[c + 2], s1.z); atomicAdd(&g_sums[c + 3], s1.w);
        atomicAdd(&g_sums[512 + c + 0], s2.x); atomicAdd(&g_sums[512 + c + 1], s2.y);
        atomicAdd(&g_sums[512 + c + 2], s2.z); atomicAdd(&g_sums[512 + c + 3], s2.w);
    }
    // barrier 1
    __syncthreads(); __threadfence();
    if (t == 0) { atomicAdd(&g_bar1, 1u); while (atomicAdd(&g_bar1, 0u) < 296u) { } }
    __syncthreads();
    // ---- phase B: eqkv transform ----
    for (int idx = bx*128 + t; idx < MM_*DD_/4; idx += 296*128) {
        int c = (idx*4) & 511;
        float4 sm = *(const float4*)&g_sums[c];
        float4 sq = *(const float4*)&g_sums[512 + c];
        float4 hv = ((const float4*)g_hconv)[idx];
        float4 qv = ((const float4*)Q)[idx];
        float4 kv = ((const float4*)Kin)[idx];
        float4 vv = ((const float4*)Vin)[idx];
        float4 eq, ek, ev;
#define BN1(comp) { \
        float mu = sm.comp * (1.f/1568.f); \
        float var = sq.comp * (1.f/1568.f) - mu*mu; \
        float xn = fmaxf((hv.comp - mu) * rsqrtf(var + EPSV_), 0.f); \
        eq.comp = to_tf32(xn + qv.comp); \
        ek.comp = to_tf32(xn + kv.comp); \
        ev.comp = to_tf32(xn + vv.comp); }
        BN1(x) BN1(y) BN1(z) BN1(w)
#undef BN1
        ((float4*)g_eq)[idx] = eq;
        ((float4*)g_ek)[idx] = ek;
        ((float4*)g_ev)[idx] = ev;
    }
    // barrier 2
    __syncthreads(); __threadfence();
    if (t == 0) { atomicAdd(&g_bar2, 1u); while (atomicAdd(&g_bar2, 0u) < 296u) { } }
    __syncthreads();
    // ---- phase C: GEMM tiles (work-steal over 312 tiles) ----
    for (int tile = bx; tile < 312; tile += 296) {
        __syncthreads();   // protect smem ring reuse across calls
        int z, lx;
        if (tile < 130)      { z = 0; lx = tile; }
        else if (tile < 260) { z = 1; lx = tile - 130; }
        else                 { z = 2; lx = tile - 260; }
        int m0, n0;
        if (z < 2) { n0 = (lx % 10)*BNT; m0 = (lx / 10)*BMT; }
        else       { n0 = (lx & 3)*BNT;  m0 = (lx >> 2)*BMT; }
        const float* A    = z == 0 ? g_eq    : z == 1 ? g_ek    : g_ev;
        const float* Bm   = z == 0 ? g_Bq    : z == 1 ? g_Bk    : g_Wvr;
        const float* bias = z == 0 ? g_biasq : z == 1 ? g_biask : bv;
        float*       C    = z == 0 ? g_eqcat : z == 1 ? g_ekcat : g_v;
        int N = z < 2 ? 1280 : 512;
        gemm_core<false, false>(A, Bm, bias, C, MM_, N, 512, 0, 16, 0, 0,
                                m0, n0, 0, sm_gemm, sm_gemm + 3*BMT*APAD);
    }
    // reset barrier counters for graph replay
    __syncthreads();
    if (t == 0) {
        unsigned v = atomicAdd(&g_bar3, 1u);
        if (v == 295u) { g_bar1 = 0u; g_bar2 = 0u; g_bar3 = 0u; __threadfence(); }
    }
}

// output projection, split-K=4, atomic into pre-zeroed d_out
__global__ void __launch_bounds__(128, 2)
rea_gout(const float* __restrict__ A, const float* __restrict__ Bm,
         const float* __restrict__ bias, float* __restrict__ C) {
    gemm_core<false, true>(A, Bm, bias, C, MM_, 512, 512,
                           blockIdx.z*128, 4, 0, 0,
                           blockIdx.y*BMT, blockIdx.x*BNT, blockIdx.z,
                           sm_gemm, sm_gemm + 3*BMT*APAD);
}

// ---------------- per-pair gate v4: smem-resident tiles + packed FFMA2 -------
// grid (32, 10), 256 threads: block handles pairs [by*256, by*256+256) of batch b.
// Dynamic smem: ck[512*49] | aq[512*7] | wpk[3584] | abp[1024]  (130 KB)
#define PAIR_SMEM ((512*49 + 512*7 + 3584 + 1024)*4)
extern __shared__ float ps_pair[];
__global__ void __launch_bounds__(256)
rea_pair(const float* __restrict__ Wc2, const float* __restrict__ bc1,
         const float* __restrict__ gc, const float* __restrict__ bcln,
         const float* __restrict__ bc2, const float* __restrict__ br1,
         const float* __restrict__ gr, const float* __restrict__ brln) {
    float* ck  = ps_pair;             // 25088
    float* aq  = ck + 512*49;         // 3584
    float* wpk = aq + 512*7;          // 3584 (channel Wc2 packed / relation w2g)
    float* abp = wpk + 3584;          // 1024 (LN params packed per j-pair)
    __shared__ float s_bc2[16], s_reg[16];

    int b = blockIdx.x, by = blockIdx.y;
    int t = threadIdx.x;
    int p = by*256 + t;
    int q = p / 49, k = p - q*49;
    bool act = q < 49;
    int qc = act ? q : 48;
    int qbase = (by*256) / 49;
    int ql = qc - qbase;              // 0..6 (safe for inactive lanes too)
    int qn = min(7, 49 - qbase);
    int b49 = b*49;

    if (t < NRELV_) { s_bc2[t] = bc2[t]; s_reg[t] = g_reg[t]; }

    // ================== channel branch (256 dims, offset 512) ==================
    for (int idx = t; idx < 49*256; idx += 256) {
        int kk = idx >> 8, j = idx & 255;
        ck[j*49 + kk] = g_ekcat[(size_t)(b49 + kk)*1280 + 512 + j];
    }
    for (int idx = t; idx < qn*256; idx += 256) {
        int r = idx >> 8, j = idx & 255;
        aq[j*7 + r] = g_eqcat[(size_t)(b49 + qbase + r)*1280 + 512 + j] + bc1[j];
    }
    for (int idx = t; idx < 3584; idx += 256) {
        int j2 = idx / 28, r = idx - j2*28;
        int tt = r >> 1, e = r & 1;
        wpk[idx] = Wc2[(size_t)(2*j2 + e)*14 + tt];
    }
    for (int idx = t; idx < 512; idx += 256) {
        int j2 = idx >> 2, r = idx & 3;
        int e = r >> 1;
        abp[idx] = (r & 1) ? bcln[2*j2 + e] : gc[2*j2 + e];
    }
    __syncthreads();

    // stats sweep
    float s1 = 0.f, s2 = 0.f;
#pragma unroll 8
    for (int j = 0; j < 256; j++) {
        float x = aq[j*7 + ql] + ck[j*49 + k];
        s1 += x; s2 = fmaf(x, x, s2);
    }
    float mu = s1 * (1.f/256.f);
    float rs = rsqrtf(s2*(1.f/256.f) - mu*mu + EPSV_);

    // logit sweep: packed FFMA2, 14 accumulator pairs
    ull lg2[14];
#pragma unroll
    for (int i = 0; i < 14; i++) lg2[i] = 0ull;
#pragma unroll 2
    for (int j2 = 0; j2 < 128; j2++) {
        float a0 = aq[(2*j2)*7 + ql],   a1 = aq[(2*j2 + 1)*7 + ql];
        float c0 = ck[(2*j2)*49 + k],   c1 = ck[(2*j2 + 1)*49 + k];
        float4 ab = *(const float4*)&abp[j2*4];
        float A0 = rs*ab.x, A1 = rs*ab.z;
        float y0 = fmaxf(fmaf(a0 + c0, A0, ab.y - mu*A0), 0.f);
        float y1 = fmaxf(fmaf(a1 + c1, A1, ab.w - mu*A1), 0.f);
        ull y2 = pk2(y0, y1);
        const ulonglong2* wp = (const ulonglong2*)(wpk + j2*28);
#pragma unroll
        for (int i = 0; i < 7; i++) {
            ulonglong2 w = wp[i];
            lg2[2*i]     = fma2v(y2, w.x, lg2[2*i]);
            lg2[2*i + 1] = fma2v(y2, w.y, lg2[2*i + 1]);
        }
    }
    float mx = -1e30f;
    float lgf[14];
#pragma unroll
    for (int tt = 0; tt < 14; tt++) {
        float e0, e1; upk2(lg2[tt], e0, e1);
        lgf[tt] = e0 + e1 + s_bc2[tt];
        mx = fmaxf(mx, lgf[tt]);
    }
    float se = 0.f, dg = 0.f;
#pragma unroll
    for (int tt = 0; tt < 14; tt++) {
        float e = expf(lgf[tt] - mx); se += e; dg += e*s_reg[tt];
    }
    float proj = dg / se * (1.f/(1.f + 1e-8f));   // top_k over all 14 == identity

    // ================== relation branch (512 dims, offset 768) =================
    __syncthreads();
    for (int idx = t; idx < 49*512; idx += 256) {
        int kk = idx >> 9, j = idx & 511;
        ck[j*49 + kk] = g_ekcat[(size_t)(b49 + kk)*1280 + 768 + j];
    }
    for (int idx = t; idx < qn*512; idx += 256) {
        int r = idx >> 9, j = idx & 511;
        aq[j*7 + r] = g_eqcat[(size_t)(b49 + qbase + r)*1280 + 768 + j] + br1[j];
    }
    for (int idx = t; idx < 512; idx += 256) wpk[idx] = g_wr2g[idx];
    for (int idx = t; idx < 1024; idx += 256) {
        int j2 = idx >> 2, r = idx & 3;
        int e = r >> 1;
        abp[idx] = (r & 1) ? brln[2*j2 + e] : gr[2*j2 + e];
    }
    __syncthreads();

    s1 = 0.f; s2 = 0.f;
#pragma unroll 8
    for (int j = 0; j < 512; j++) {
        float x = aq[j*7 + ql] + ck[j*49 + k];
        s1 += x; s2 = fmaf(x, x, s2);
    }
    float mur = s1 * (1.f/512.f);
    float rsr = rsqrtf(s2*(1.f/512.f) - mur*mur + EPSV_);

    ull dr2 = 0ull;
#pragma unroll 4
    for (int j2 = 0; j2 < 256; j2++) {
        float a0 = aq[(2*j2)*7 + ql],   a1 = aq[(2*j2 + 1)*7 + ql];
        float c0 = ck[(2*j2)*49 + k],   c1 = ck[(2*j2 + 1)*49 + k];
        float4 ab = *(const float4*)&abp[j2*4];
        float A0 = rsr*ab.x, A1 = rsr*ab.z;
        float y0 = fmaxf(fmaf(a0 + c0, A0, ab.y - mur*A0), 0.f);
        float y1 = fmaxf(fmaf(a1 + c1, A1, ab.w - mur*A1), 0.f);
        ull y2 = pk2(y0, y1);
        ull w2 = *(const ull*)(wpk + 2*j2);
        dr2 = fma2v(y2, w2, dr2);
    }
    float d0, d1; upk2(dr2, d0, d1);
    float dr = d0 + d1;

    if (act) {
        float ga = dr + proj + g_c0[0];
        g_gate[(size_t)(b49 + q)*49 + k] = 1.f/(1.f + expf(-ga));
    }
}

// ---------------- attention per (b,h); also zeroes d_out for atomic gout ----
__global__ void __launch_bounds__(256)
rea_attn(float* __restrict__ out, float* __restrict__ dz) {
    __shared__ float Qt[49*65], Kt[49*65], Vt[49*65];
    __shared__ float wrow[8][52];
    int h = blockIdx.x, b = blockIdx.y;
    int t = threadIdx.x, w = t >> 5, l = t & 31;

    {
        float4 z4 = make_float4(0.f, 0.f, 0.f, 0.f);
        float4* dst = (float4*)dz + (size_t)(b*8 + h)*784;
        for (int i = t; i < 784; i += 256) dst[i] = z4;
    }

    for (int idx = t; idx < 49*64; idx += 256) {
        int q = idx >> 6, d = idx & 63;
        Qt[q*65 + d] = g_eqcat[(size_t)(b*49 + q)*1280 + h*64 + d];
        Kt[q*65 + d] = g_ekcat[(size_t)(b*49 + q)*1280 + h*64 + d];
        Vt[q*65 + d] = g_v[(size_t)(b*49 + q)*512 + h*64 + d];
    }
    __syncthreads();

    for (int q = w; q < 49; q += 8) {
        int m = b*49 + q;
        int k2 = l + 32;
        bool v2 = k2 < 49;
        float g1 = g_gate[(size_t)m*49 + l];
        float g2 = v2 ? g_gate[(size_t)m*49 + k2] : 0.f;
        const float* qr  = Qt + q*65;
        const float* k1r = Kt + l*65;
        const float* k2r = Kt + (v2 ? k2 : l)*65;
        float d1 = 0.f, d2 = 0.f;
#pragma unroll 8
        for (int d = 0; d < 64; d++) {
            float qv = qr[d];
            d1 += qv * k1r[d];
            d2 += qv * k2r[d];
        }
        float lv1 = d1*SCALEV_*(1.f + g1);
        float lv2 = v2 ? d2*SCALEV_*(1.f + g2) : -1e30f;
        float mx = fmaxf(lv1, lv2);
#pragma unroll
        for (int o = 16; o > 0; o >>= 1) mx = fmaxf(mx, __shfl_xor_sync(0xffffffffu, mx, o));
        float e1 = expf(lv1 - mx);
        float e2 = v2 ? expf(lv2 - mx) : 0.f;
        float ssum = wsum(e1 + e2);
        float inv = 1.f / ssum;
        wrow[w][l] = e1 * inv;
        if (v2) wrow[w][k2] = e2 * inv;
        __syncwarp();
        float a1 = 0.f, a2 = 0.f;
        for (int k = 0; k < 49; k++) {
            float wk = wrow[w][k];
            a1 += wk * Vt[k*65 + l];
            a2 += wk * Vt[k*65 + l + 32];
        }
        out[(size_t)m*512 + h*64 + l]      = to_tf32(a1);
        out[(size_t)m*512 + h*64 + l + 32] = to_tf32(a2);
        __syncwarp();
    }
}

// ---------------- launch ----------------
extern "C" void kernel_launch(void* const* d_in, const int* in_sizes, int n_in,
                              void* d_out, int out_size) {
    const float* Q     = (const float*)d_in[0];
    const float* Kin   = (const float*)d_in[1];
    const float* Vin   = (const float*)d_in[2];
    const float* Wq    = (const float*)d_in[3];
    const float* bq    = (const float*)d_in[4];
    const float* Wk    = (const float*)d_in[5];
    const float* bk    = (const float*)d_in[6];
    const float* Wv    = (const float*)d_in[7];
    const float* bv    = (const float*)d_in[8];
    const float* Wo    = (const float*)d_in[9];
    const float* bo    = (const float*)d_in[10];
    const float* rel   = (const float*)d_in[11];
    const float* Wproj = (const float*)d_in[12];
    const float* bproj = (const float*)d_in[13];
    const float* Wgate = (const float*)d_in[14];
    const float* bgate = (const float*)d_in[15];
    const float* Wc1   = (const float*)d_in[16];
    const float* bc1   = (const float*)d_in[17];
    const float* gc    = (const float*)d_in[18];
    const float* bcln  = (const float*)d_in[19];
    const float* Wc2   = (const float*)d_in[20];
    const float* bc2   = (const float*)d_in[21];
    const float* Wr1   = (const float*)d_in[22];
    const float* br1   = (const float*)d_in[23];
    const float* gr    = (const float*)d_in[24];
    const float* brln  = (const float*)d_in[25];
    const float* Wr2   = (const float*)d_in[26];
    const float* br2   = (const float*)d_in[27];
    const float* convW = (const float*)d_in[28];
    const float* convb = (const float*)d_in[29];

    void *p_qr, *p_att, *p_convWt, *p_Wor;
    cudaGetSymbolAddress(&p_qr, g_qr);
    cudaGetSymbolAddress(&p_att, g_att);
    cudaGetSymbolAddress(&p_convWt, g_convWt);
    cudaGetSymbolAddress(&p_Wor, g_Wor);

    static bool attr_set = false;
    if (!attr_set) {
        cudaFuncSetAttribute(rea_gconv, cudaFuncAttributeMaxDynamicSharedMemorySize, GEMM_SMEM);
        cudaFuncSetAttribute(rea_gqkv, cudaFuncAttributeMaxDynamicSharedMemorySize, GEMM_SMEM);
        cudaFuncSetAttribute(rea_gout, cudaFuncAttributeMaxDynamicSharedMemorySize, GEMM_SMEM);
        cudaFuncSetAttribute(rea_pair, cudaFuncAttributeMaxDynamicSharedMemorySize, PAIR_SMEM);
        attr_set = true;
    }

    // 6 launches; ncu captures launch idx 3 => rea_pair this round
    rea_prologue<<<3665, 256>>>(convW, Q, Wr2, Wproj, Wgate, rel, br2, bproj, bgate,
                                Wq, Wk, Wc1, Wr1, bq, bk, Wv, Wo);
    rea_gconv<<<dim3(4, 13, 9), 128, GEMM_SMEM>>>((const float*)p_qr,
                                                  (const float*)p_convWt, convb);
    rea_gqkv<<<296, 128, GEMM_SMEM>>>(bv, Q, Kin, Vin);

    rea_pair<<<dim3(32, 10), 256, PAIR_SMEM>>>(Wc2, bc1, gc, bcln, bc2, br1, gr, brln);

    rea_attn<<<dim3(8, 32), 256>>>((float*)p_att, (float*)d_out);

    rea_gout<<<dim3(4, 13, 4), 128, GEMM_SMEM>>>((const float*)p_att, (const float*)p_Wor,
                                                 bo, (float*)d_out);
}

// round 13
// speedup vs baseline: 1.2345x; 1.1646x over previous
#include <cuda_runtime.h>
#include <math.h>
#include <stdint.h>

// Problem constants
#define BB_ 32
#define NN_ 49
#define DD_ 512
#define MM_ (BB_*NN_)      // 1568
#define NRELV_ 14
#define EPSV_ 1e-5f
#define SCALEV_ 0.125f     // 1/sqrt(64)

typedef unsigned long long ull;

// ---------------- device scratch (no allocations allowed) ----------------
__device__ __align__(256) float g_hconv[MM_*DD_];
__device__ __align__(256) float g_qr[MM_*DD_];
__device__ __align__(256) float g_eq[MM_*DD_];
__device__ __align__(256) float g_ek[MM_*DD_];
__device__ __align__(256) float g_ev[MM_*DD_];
__device__ __align__(256) float g_eqcat[MM_*1280];
__device__ __align__(256) float g_ekcat[MM_*1280];
__device__ __align__(256) float g_v[MM_*DD_];
__device__ __align__(256) float g_att[MM_*DD_];
__device__ __align__(256) float g_convWt[9*512*512];
__device__ __align__(256) float g_Bq[512*1280];
__device__ __align__(256) float g_Bk[512*1280];
__device__ __align__(256) float g_Wvr[512*512];
__device__ __align__(256) float g_Wor[512*512];
__device__ __align__(256) float g_biasq[1280];
__device__ __align__(256) float g_biask[1280];
__device__ float g_sums[1024];
__device__ float g_wr2g[512];
__device__ float g_reg[NRELV_];
__device__ float g_c0[1];
__device__ float g_gate[MM_*NN_];
__device__ unsigned g_bar1 = 0;
__device__ unsigned g_bar2 = 0;
__device__ unsigned g_bar3 = 0;

__device__ __forceinline__ float wsum(float v) {
#pragma unroll
    for (int o = 16; o > 0; o >>= 1) v += __shfl_xor_sync(0xffffffffu, v, o);
    return v;
}

__device__ __forceinline__ float to_tf32(float x) {
    uint32_t u;
    asm("cvt.rna.tf32.f32 %0, %1;" : "=r"(u) : "f"(x));
    return __uint_as_float(u);
}

__device__ __forceinline__ void mma_tf32(float* c,
                                         uint32_t a0, uint32_t a1, uint32_t a2, uint32_t a3,
                                         uint32_t b0, uint32_t b1) {
    asm volatile("mma.sync.aligned.m16n8k8.row.col.f32.tf32.tf32.f32 "
                 "{%0,%1,%2,%3}, {%4,%5,%6,%7}, {%8,%9}, {%0,%1,%2,%3};"
                 : "+f"(c[0]), "+f"(c[1]), "+f"(c[2]), "+f"(c[3])
                 : "r"(a0), "r"(a1), "r"(a2), "r"(a3), "r"(b0), "r"(b1));
}

__device__ __forceinline__ void cp16(uint32_t dst, const float* src, bool pred) {
    int sz = pred ? 16 : 0;
    asm volatile("cp.async.cg.shared.global [%0], [%1], 16, %2;\n"
                 :: "r"(dst), "l"(src), "r"(sz));
}
#define CP_COMMIT() asm volatile("cp.async.commit_group;" ::: "memory")
#define CP_WAIT1()  asm volatile("cp.async.wait_group 1;" ::: "memory")

// packed f32x2 helpers (sm_103a FFMA2)
__device__ __forceinline__ ull pk2(float a, float b) {
    ull r; asm("mov.b64 %0, {%1, %2};" : "=l"(r) : "f"(a), "f"(b)); return r;
}
__device__ __forceinline__ void upk2(ull v, float& a, float& b) {
    asm("mov.b64 {%0, %1}, %2;" : "=f"(a), "=f"(b) : "l"(v));
}
__device__ __forceinline__ ull fma2v(ull a, ull b, ull c) {
    ull d; asm("fma.rn.f32x2 %0, %1, %2, %3;" : "=l"(d) : "l"(a), "l"(b), "l"(c));
    return d;
}

// ---------------- fused prologue: conv repack + Q round/hconv zero + k0 + bcat
__global__ void __launch_bounds__(256)
rea_prologue(const float* __restrict__ convW, const float* __restrict__ Q,
             const float* __restrict__ Wr2, const float* __restrict__ Wproj,
             const float* __restrict__ Wg, const float* __restrict__ rel,
             const float* __restrict__ br2, const float* __restrict__ bproj,
             const float* __restrict__ bgate,
             const float* __restrict__ Wq, const float* __restrict__ Wk,
             const float* __restrict__ Wc1, const float* __restrict__ Wr1,
             const float* __restrict__ bq, const float* __restrict__ bk,
             const float* __restrict__ Wv, const float* __restrict__ Wo) {
    int bx = blockIdx.x, t = threadIdx.x;
    if (bx < 256) {
        __shared__ float ts[32*289];
        int o0 = (bx & 15)*32, c0 = (bx >> 4)*32;
        for (int idx = t; idx < 32*288; idx += 256) {
            int o = idx / 288, r = idx - o*288;   // r = c_local*9 + tap
            ts[o*289 + r] = to_tf32(convW[((size_t)(o0 + o)*512 + c0)*9 + r]);
        }
        __syncthreads();
        for (int idx = t; idx < 288*32; idx += 256) {
            int row = idx >> 5, o = idx & 31;
            int c = row / 9, tap = row - c*9;
            g_convWt[(size_t)tap*262144 + (size_t)(c0 + c)*512 + o0 + o] = ts[o*289 + row];
        }
    } else if (bx < 1040) {
        int idx = (bx - 256)*256 + t;
        if (idx < MM_*DD_/4) {
            float4 qv = ((const float4*)Q)[idx];
            float4 r;
            r.x = to_tf32(qv.x); r.y = to_tf32(qv.y);
            r.z = to_tf32(qv.z); r.w = to_tf32(qv.w);
            ((float4*)g_qr)[idx] = r;
            ((float4*)g_hconv)[idx] = make_float4(0.f, 0.f, 0.f, 0.f);
        }
        if (bx == 256)
            ((float4*)g_sums)[t] = make_float4(0.f, 0.f, 0.f, 0.f);
    } else if (bx < 1105) {
        __shared__ float wg_s[512];
        __shared__ float wpg_s[64];
        int kb = bx - 1040;
        wg_s[t] = Wg[t];
        wg_s[t + 256] = Wg[t + 256];
        __syncthreads();
        int w = t >> 5, l = t & 31;
        if (kb < 64) {
            int row = kb*8 + w;
            float s = 0.f;
            for (int j = l; j < 512; j += 32) s += Wr2[(size_t)row*512 + j] * wg_s[j];
            s = wsum(s);
            if (l == 0) g_wr2g[row] = s;
        } else {
            for (int r = w; r < 64; r += 8) {
                float s = 0.f;
                for (int j = l; j < 512; j += 32) s += Wproj[(size_t)r*512 + j] * wg_s[j];
                s = wsum(s);
                if (l == 0) wpg_s[r] = s;
            }
            __syncthreads();
            if (t < NRELV_) {
                float s = 0.f;
                for (int d = 0; d < 64; d++) s += rel[t*64 + d] * wpg_s[d];
                g_reg[t] = s;
            }
            if (w == 7) {
                float s = 0.f;
                for (int j = l; j < 512; j += 32) s += (br2[j] + bproj[j]) * wg_s[j];
                s = wsum(s);
                if (l == 0) g_c0[0] = s + bgate[0];
            }
        }
    } else {
        int idx = (bx - 1105)*256 + t;
        if (idx < 512*1280) {
            int k = idx / 1280, n = idx - k*1280;
            float vq, vk;
            if (n < 512)       { vq = Wq[(size_t)k*512 + n];              vk = Wk[(size_t)k*512 + n]; }
            else if (n < 768)  { vq = Wc1[(size_t)k*256 + (n-512)];       vk = Wc1[(size_t)(k+512)*256 + (n-512)]; }
            else               { vq = Wr1[(size_t)k*512 + (n-768)];       vk = Wr1[(size_t)(k+512)*512 + (n-768)]; }
            g_Bq[idx] = to_tf32(vq); g_Bk[idx] = to_tf32(vk);
        }
        if (idx < 512*512) {
            g_Wvr[idx] = to_tf32(Wv[idx]);
            g_Wor[idx] = to_tf32(Wo[idx]);
        }
        if (idx < 1280) {
            g_biasq[idx] = idx < 512 ? bq[idx] : 0.f;
            g_biask[idx] = idx < 512 ? bk[idx] : 0.f;
        }
    }
}

// ---------------- TF32 tensor-core GEMM core ----------------
#define BMT 128
#define BNT 128
#define BKT 32
#define APAD 36
#define BPAD 136
#define SZA (BMT*APAD*4)
#define SZB (BKT*BPAD*4)
#define GEMM_SMEM (3*(BMT*APAD + BKT*BPAD)*4)

template <bool CONV, bool ATOMIC>
__device__ __forceinline__ void gemm_core(
    const float* __restrict__ A, const float* __restrict__ Bm,
    const float* __restrict__ bias, float* __restrict__ C,
    int M, int N, int lda, int kbase, int KT, int di, int dj,
    int m0, int n0, int zz,
    float* AsB, float* BsB) {

    int tid = threadIdx.x;
    int lane = tid & 31, warp = tid >> 5;
    int g = lane >> 2, t4 = lane & 3;
    int wm = (warp & 1) * 64, wn = (warp >> 1) * 64;

    uint32_t sA = (uint32_t)__cvta_generic_to_shared(AsB);
    uint32_t sB = (uint32_t)__cvta_generic_to_shared(BsB);

    float acc[4][8][4];
#pragma unroll
    for (int i = 0; i < 4; i++)
#pragma unroll
        for (int j = 0; j < 8; j++)
#pragma unroll
            for (int q = 0; q < 4; q++) acc[i][j][q] = 0.f;

    const float* aptr[8]; bool apred[8]; uint32_t adst[8];
    const float* bptr0; uint32_t bdst0;
#pragma unroll
    for (int h = 0; h < 8; h++) {
        int c = tid + h*128;
        int m = c >> 3, kg = c & 7;
        int gm = m0 + m;
        bool pred;
        const float* p;
        if (!CONV) {
            pred = gm < M;
            p = A + (size_t)(pred ? gm : 0)*lda + kbase + kg*4;
        } else {
            int bb = gm / 49, pos = gm - bb*49;
            int pr = pos / 7, pc = pos - pr*7;
            int ii = pr + di, jj = pc + dj;
            pred = (gm < M) & ((unsigned)ii < 7u) & ((unsigned)jj < 7u);
            p = pred ? (A + ((size_t)(bb*49 + ii*7 + jj))*512 + kg*4) : A;
        }
        apred[h] = pred; aptr[h] = p;
        adst[h] = sA + (uint32_t)(m*APAD + kg*4)*4;
    }
    {
        int kr = tid >> 5, ng = tid & 31;
        bptr0 = Bm + (size_t)(kbase + kr)*N + n0 + ng*4;
        bdst0 = sB + (uint32_t)(kr*BPAD + ng*4)*4;
    }

    auto load_tile = [&](int kt, int buf) {
#pragma unroll
        for (int h = 0; h < 8; h++)
            cp16(adst[h] + buf*SZA, aptr[h] + kt*BKT, apred[h]);
#pragma unroll
        for (int h = 0; h < 8; h++)
            cp16(bdst0 + buf*SZB + (uint32_t)h*4*BPAD*4,
                 bptr0 + (size_t)(kt*BKT + h*4)*N, true);
    };

    load_tile(0, 0); CP_COMMIT();
    if (KT > 1) load_tile(1, 1);
    CP_COMMIT();

    int buf = 0, nbuf = 2;
    for (int kt = 0; kt < KT; kt++) {
        CP_WAIT1();
        __syncthreads();
        if (kt + 2 < KT) load_tile(kt + 2, nbuf);
        CP_COMMIT();
        const float* as = AsB + buf*(BMT*APAD);
        const float* bs = BsB + buf*(BKT*BPAD);
#pragma unroll
        for (int k8 = 0; k8 < 4; k8++) {
            uint32_t af[4][4], bf[8][2];
#pragma unroll
            for (int i = 0; i < 4; i++) {
                int mrow = wm + i*16 + g;
                af[i][0] = __float_as_uint(as[mrow*APAD + k8*8 + t4]);
                af[i][1] = __float_as_uint(as[(mrow + 8)*APAD + k8*8 + t4]);
                af[i][2] = __float_as_uint(as[mrow*APAD + k8*8 + t4 + 4]);
                af[i][3] = __float_as_uint(as[(mrow + 8)*APAD + k8*8 + t4 + 4]);
            }
#pragma unroll
            for (int j = 0; j < 8; j++) {
                int nc = wn + j*8 + g;
                bf[j][0] = __float_as_uint(bs[(k8*8 + t4)*BPAD + nc]);
                bf[j][1] = __float_as_uint(bs[(k8*8 + t4 + 4)*BPAD + nc]);
            }
#pragma unroll
            for (int i = 0; i < 4; i++)
#pragma unroll
                for (int j = 0; j < 8; j++)
                    mma_tf32(acc[i][j], af[i][0], af[i][1], af[i][2], af[i][3],
                             bf[j][0], bf[j][1]);
        }
        buf = (buf == 2) ? 0 : buf + 1;
        nbuf = (nbuf == 2) ? 0 : nbuf + 1;
    }

#pragma unroll
    for (int i = 0; i < 4; i++) {
        int mbase = m0 + wm + i*16 + g;
#pragma unroll
        for (int half = 0; half < 2; half++) {
            int gm = mbase + half*8;
            if (gm < M) {
#pragma unroll
                for (int j = 0; j < 8; j++) {
                    int gn = n0 + wn + j*8 + t4*2;
                    float v0 = acc[i][j][half*2 + 0];
                    float v1 = acc[i][j][half*2 + 1];
                    if (ATOMIC) {
                        if (zz == 0 && bias) { v0 += bias[gn]; v1 += bias[gn + 1]; }
                        atomicAdd(&C[(size_t)gm*N + gn],     v0);
                        atomicAdd(&C[(size_t)gm*N + gn + 1], v1);
                    } else {
                        if (bias) { v0 += bias[gn]; v1 += bias[gn + 1]; }
                        C[(size_t)gm*N + gn]     = v0;
                        C[(size_t)gm*N + gn + 1] = v1;
                    }
                }
            }
        }
    }
}

extern __shared__ float sm_gemm[];

// conv as implicit GEMM, split-K=9, atomic accumulate into pre-zeroed hconv
__global__ void __launch_bounds__(128, 2)
rea_gconv(const float* __restrict__ A, const float* __restrict__ Bm,
          const float* __restrict__ bias) {
    int tap = blockIdx.z;
    gemm_core<true, true>(A, Bm, bias, g_hconv, MM_, 512, 512,
                          tap*512, 16, tap/3 - 1, tap%3 - 1,
                          blockIdx.y*BMT, blockIdx.x*BNT, tap,
                          sm_gemm, sm_gemm + 3*BMT*APAD);
}

// fused: BN stats | bar | eqkv | bar | eq/ek/ev projections (296 blocks resident)
__global__ void __launch_bounds__(128, 2)
rea_gqkv(const float* __restrict__ bv, const float* __restrict__ Q,
         const float* __restrict__ Kin, const float* __restrict__ Vin) {
    int bx = blockIdx.x, t = threadIdx.x;
    if (bx < 98) {
        float4 s1 = make_float4(0.f, 0.f, 0.f, 0.f);
        float4 s2 = make_float4(0.f, 0.f, 0.f, 0.f);
#pragma unroll
        for (int it = 0; it < 16; it++) {
            float4 a = ((const float4*)g_hconv)[(size_t)(bx*16 + it)*128 + t];
            s1.x += a.x; s1.y += a.y; s1.z += a.z; s1.w += a.w;
            s2.x = fmaf(a.x, a.x, s2.x); s2.y = fmaf(a.y, a.y, s2.y);
            s2.z = fmaf(a.z, a.z, s2.z); s2.w = fmaf(a.w, a.w, s2.w);
        }
        int c = t*4;
        atomicAdd(&g_sums[c + 0], s1.x); atomicAdd(&g_sums[c + 1], s1.y);
        atomicAdd(&g_sums[c + 2], s1.z); atomicAdd(&g_sums[c + 3], s1.w);
        atomicAdd(&g_sums[512 + c + 0], s2.x); atomicAdd(&g_sums[512 + c + 1], s2.y);
        atomicAdd(&g_sums[512 + c + 2], s2.z); atomicAdd(&g_sums[512 + c + 3], s2.w);
    }
    __syncthreads(); __threadfence();
    if (t == 0) { atomicAdd(&g_bar1, 1u); while (atomicAdd(&g_bar1, 0u) < 296u) { } }
    __syncthreads();
    for (int idx = bx*128 + t; idx < MM_*DD_/4; idx += 296*128) {
        int c = (idx*4) & 511;
        float4 sm = *(const float4*)&g_sums[c];
        float4 sq = *(const float4*)&g_sums[512 + c];
        float4 hv = ((const float4*)g_hconv)[idx];
        float4 qv = ((const float4*)Q)[idx];
        float4 kv = ((const float4*)Kin)[idx];
        float4 vv = ((const float4*)Vin)[idx];
        float4 eq, ek, ev;
#define BN1(comp) { \
        float mu = sm.comp * (1.f/1568.f); \
        float var = sq.comp * (1.f/1568.f) - mu*mu; \
        float xn = fmaxf((hv.comp - mu) * rsqrtf(var + EPSV_), 0.f); \
        eq.comp = to_tf32(xn + qv.comp); \
        ek.comp = to_tf32(xn + kv.comp); \
        ev.comp = to_tf32(xn + vv.comp); }
        BN1(x) BN1(y) BN1(z) BN1(w)
#undef BN1
        ((float4*)g_eq)[idx] = eq;
        ((float4*)g_ek)[idx] = ek;
        ((float4*)g_ev)[idx] = ev;
    }
    __syncthreads(); __threadfence();
    if (t == 0) { atomicAdd(&g_bar2, 1u); while (atomicAdd(&g_bar2, 0u) < 296u) { } }
    __syncthreads();
    for (int tile = bx; tile < 312; tile += 296) {
        __syncthreads();
        int z, lx;
        if (tile < 130)      { z = 0; lx = tile; }
        else if (tile < 260) { z = 1; lx = tile - 130; }
        else                 { z = 2; lx = tile - 260; }
        int m0, n0;
        if (z < 2) { n0 = (lx % 10)*BNT; m0 = (lx / 10)*BMT; }
        else       { n0 = (lx & 3)*BNT;  m0 = (lx >> 2)*BMT; }
        const float* A    = z == 0 ? g_eq    : z == 1 ? g_ek    : g_ev;
        const float* Bm   = z == 0 ? g_Bq    : z == 1 ? g_Bk    : g_Wvr;
        const float* bias = z == 0 ? g_biasq : z == 1 ? g_biask : bv;
        float*       C    = z == 0 ? g_eqcat : z == 1 ? g_ekcat : g_v;
        int N = z < 2 ? 1280 : 512;
        gemm_core<false, false>(A, Bm, bias, C, MM_, N, 512, 0, 16, 0, 0,
                                m0, n0, 0, sm_gemm, sm_gemm + 3*BMT*APAD);
    }
    __syncthreads();
    if (t == 0) {
        unsigned v = atomicAdd(&g_bar3, 1u);
        if (v == 295u) { g_bar1 = 0u; g_bar2 = 0u; g_bar3 = 0u; __threadfence(); }
    }
}

// output projection, split-K=4, atomic into pre-zeroed d_out
__global__ void __launch_bounds__(128, 2)
rea_gout(const float* __restrict__ A, const float* __restrict__ Bm,
         const float* __restrict__ bias, float* __restrict__ C) {
    gemm_core<false, true>(A, Bm, bias, C, MM_, 512, 512,
                           blockIdx.z*128, 4, 0, 0,
                           blockIdx.y*BMT, blockIdx.x*BNT, blockIdx.z,
                           sm_gemm, sm_gemm + 3*BMT*APAD);
}

// ---------------- per-pair gate v5: k-major float4 tiles, 3 CTA/SM ----------
// grid (32, 10), 256 threads, JT=128 j-tiles; static smem ~39 KB.
#define JT 128
#define CKP 132   // row pad: float4 stride 33 -> conflict-free lane-k reads
__global__ void __launch_bounds__(256, 3)
rea_pair(const float* __restrict__ Wc2, const float* __restrict__ bc1,
         const float* __restrict__ gc, const float* __restrict__ bcln,
         const float* __restrict__ bc2, const float* __restrict__ br1,
         const float* __restrict__ gr, const float* __restrict__ brln) {
    __shared__ float ckt[49*CKP];     // 25.9 KB
    __shared__ float aqt[7*CKP];      // 3.7 KB
    __shared__ float wpk[64*28];      // 7 KB (channel Wc2 packed per j2)
    __shared__ float abp[64*4];       // 1 KB (LN params packed per j2)
    __shared__ float w2t[JT];         // relation weights tile
    __shared__ float s_bc2[16], s_reg[16];

    int b = blockIdx.x, by = blockIdx.y;
    int t = threadIdx.x;
    int p = by*256 + t;
    int q = p / 49, k = p - q*49;
    bool act = q < 49;
    int qc = act ? q : 48;
    int qbase = (by*256) / 49;
    int ql = qc - qbase;
    int qn = min(7, 49 - qbase);
    int b49 = b*49;

    if (t < NRELV_) { s_bc2[t] = bc2[t]; s_reg[t] = g_reg[t]; }

    // helper lambdas for tile fills
    auto fill_ck = [&](int off, int j0) {
        for (int idx = t; idx < 49*32; idx += 256) {
            int kk = idx >> 5, j4 = idx & 31;
            float4 v = *(const float4*)&g_ekcat[(size_t)(b49 + kk)*1280 + off + j0 + j4*4];
            *(float4*)&ckt[kk*CKP + j4*4] = v;
        }
    };
    auto fill_aq = [&](int off, int j0, const float* bias) {
        for (int idx = t; idx < qn*32; idx += 256) {
            int r = idx >> 5, j4 = idx & 31;
            float4 v = *(const float4*)&g_eqcat[(size_t)(b49 + qbase + r)*1280 + off + j0 + j4*4];
            float4 bb = *(const float4*)&bias[j0 + j4*4];
            v.x += bb.x; v.y += bb.y; v.z += bb.z; v.w += bb.w;
            *(float4*)&aqt[r*CKP + j4*4] = v;
        }
    };

    // ================== channel branch (256 dims, offset 512) ==================
    float s1 = 0.f, s2 = 0.f;
    for (int jt = 0; jt < 2; jt++) {
        __syncthreads();
        fill_ck(512, jt*JT);
        fill_aq(512, jt*JT, bc1);
        __syncthreads();
#pragma unroll 4
        for (int j4 = 0; j4 < 32; j4++) {
            float4 c4 = *(float4*)&ckt[k*CKP + j4*4];
            float4 a4 = *(float4*)&aqt[ql*CKP + j4*4];
            float x0 = a4.x + c4.x, x1 = a4.y + c4.y;
            float x2 = a4.z + c4.z, x3 = a4.w + c4.w;
            s1 += x0 + x1 + x2 + x3;
            s2 = fmaf(x0, x0, s2); s2 = fmaf(x1, x1, s2);
            s2 = fmaf(x2, x2, s2); s2 = fmaf(x3, x3, s2);
        }
    }
    float mu = s1 * (1.f/256.f);
    float rs = rsqrtf(s2*(1.f/256.f) - mu*mu + EPSV_);

    ull lg2[14];
#pragma unroll
    for (int i = 0; i < 14; i++) lg2[i] = 0ull;
    for (int jt = 0; jt < 2; jt++) {
        int j0 = jt*JT;
        __syncthreads();
        fill_ck(512, j0);
        fill_aq(512, j0, bc1);
        for (int idx = t; idx < 64*28; idx += 256) {
            int j2 = idx / 28, r = idx - j2*28;
            int tt = r >> 1, e = r & 1;
            wpk[idx] = Wc2[(size_t)(j0 + 2*j2 + e)*14 + tt];
        }
        if (t < 256) {
            int j2 = t >> 2, r = t & 3;
            int e = r >> 1;
            abp[t] = (r & 1) ? bcln[j0 + 2*j2 + e] : gc[j0 + 2*j2 + e];
        }
        __syncthreads();
#pragma unroll 2
        for (int j4 = 0; j4 < 32; j4++) {
            float4 c4 = *(float4*)&ckt[k*CKP + j4*4];
            float4 a4 = *(float4*)&aqt[ql*CKP + j4*4];
#pragma unroll
            for (int h = 0; h < 2; h++) {
                int j2 = j4*2 + h;
                float xa = h ? (a4.z + c4.z) : (a4.x + c4.x);
                float xb = h ? (a4.w + c4.w) : (a4.y + c4.y);
                float4 ab = *(const float4*)&abp[j2*4];
                float A0 = rs*ab.x, A1 = rs*ab.z;
                float y0 = fmaxf(fmaf(xa, A0, ab.y - mu*A0), 0.f);
                float y1 = fmaxf(fmaf(xb, A1, ab.w - mu*A1), 0.f);
                ull y2 = pk2(y0, y1);
                const ulonglong2* wp = (const ulonglong2*)&wpk[j2*28];
#pragma unroll
                for (int i = 0; i < 7; i++) {
                    ulonglong2 w = wp[i];
                    lg2[2*i]     = fma2v(y2, w.x, lg2[2*i]);
                    lg2[2*i + 1] = fma2v(y2, w.y, lg2[2*i + 1]);
                }
            }
        }
    }
    float mx = -1e30f;
    float lgf[14];
#pragma unroll
    for (int tt = 0; tt < 14; tt++) {
        float e0, e1; upk2(lg2[tt], e0, e1);
        lgf[tt] = e0 + e1 + s_bc2[tt];
        mx = fmaxf(mx, lgf[tt]);
    }
    float se = 0.f, dg = 0.f;
#pragma unroll
    for (int tt = 0; tt < 14; tt++) {
        float e = expf(lgf[tt] - mx); se += e; dg += e*s_reg[tt];
    }
    float proj = dg / se * (1.f/(1.f + 1e-8f));   // top_k over all 14 == identity

    // ================== relation branch (512 dims, offset 768) =================
    s1 = 0.f; s2 = 0.f;
    for (int jt = 0; jt < 4; jt++) {
        __syncthreads();
        fill_ck(768, jt*JT);
        fill_aq(768, jt*JT, br1);
        __syncthreads();
#pragma unroll 4
        for (int j4 = 0; j4 < 32; j4++) {
            float4 c4 = *(float4*)&ckt[k*CKP + j4*4];
            float4 a4 = *(float4*)&aqt[ql*CKP + j4*4];
            float x0 = a4.x + c4.x, x1 = a4.y + c4.y;
            float x2 = a4.z + c4.z, x3 = a4.w + c4.w;
            s1 += x0 + x1 + x2 + x3;
            s2 = fmaf(x0, x0, s2); s2 = fmaf(x1, x1, s2);
            s2 = fmaf(x2, x2, s2); s2 = fmaf(x3, x3, s2);
        }
    }
    float mur = s1 * (1.f/512.f);
    float rsr = rsqrtf(s2*(1.f/512.f) - mur*mur + EPSV_);

    ull dr2 = 0ull;
    for (int jt = 0; jt < 4; jt++) {
        int j0 = jt*JT;
        __syncthreads();
        fill_ck(768, j0);
        fill_aq(768, j0, br1);
        if (t < 128) w2t[t] = g_wr2g[j0 + t];
        if (t < 256) {
            int j2 = t >> 2, r = t & 3;
            int e = r >> 1;
            abp[t] = (r & 1) ? brln[j0 + 2*j2 + e] : gr[j0 + 2*j2 + e];
        }
        __syncthreads();
#pragma unroll 4
        for (int j4 = 0; j4 < 32; j4++) {
            float4 c4 = *(float4*)&ckt[k*CKP + j4*4];
            float4 a4 = *(float4*)&aqt[ql*CKP + j4*4];
            float4 w4 = *(float4*)&w2t[j4*4];
            float4 ab0 = *(const float4*)&abp[(j4*2)*4];
            float4 ab1 = *(const float4*)&abp[(j4*2 + 1)*4];
            float A0 = rsr*ab0.x, A1 = rsr*ab0.z;
            float A2 = rsr*ab1.x, A3 = rsr*ab1.z;
            float y0 = fmaxf(fmaf(a4.x + c4.x, A0, ab0.y - mur*A0), 0.f);
            float y1 = fmaxf(fmaf(a4.y + c4.y, A1, ab0.w - mur*A1), 0.f);
            float y2 = fmaxf(fmaf(a4.z + c4.z, A2, ab1.y - mur*A2), 0.f);
            float y3 = fmaxf(fmaf(a4.w + c4.w, A3, ab1.w - mur*A3), 0.f);
            dr2 = fma2v(pk2(y0, y1), pk2(w4.x, w4.y), dr2);
            dr2 = fma2v(pk2(y2, y3), pk2(w4.z, w4.w), dr2);
        }
    }
    float d0, d1; upk2(dr2, d0, d1);
    float dr = d0 + d1;

    if (act) {
        float ga = dr + proj + g_c0[0];
        g_gate[(size_t)(b49 + q)*49 + k] = 1.f/(1.f + expf(-ga));
    }
}

// ---------------- attention per (b,h); also zeroes d_out for atomic gout ----
__global__ void __launch_bounds__(256)
rea_attn(float* __restrict__ out, float* __restrict__ dz) {
    __shared__ float Qt[49*65], Kt[49*65], Vt[49*65];
    __shared__ float wrow[8][52];
    int h = blockIdx.x, b = blockIdx.y;
    int t = threadIdx.x, w = t >> 5, l = t & 31;

    {
        float4 z4 = make_float4(0.f, 0.f, 0.f, 0.f);
        float4* dst = (float4*)dz + (size_t)(b*8 + h)*784;
        for (int i = t; i < 784; i += 256) dst[i] = z4;
    }

    for (int idx = t; idx < 49*64; idx += 256) {
        int q = idx >> 6, d = idx & 63;
        Qt[q*65 + d] = g_eqcat[(size_t)(b*49 + q)*1280 + h*64 + d];
        Kt[q*65 + d] = g_ekcat[(size_t)(b*49 + q)*1280 + h*64 + d];
        Vt[q*65 + d] = g_v[(size_t)(b*49 + q)*512 + h*64 + d];
    }
    __syncthreads();

    for (int q = w; q < 49; q += 8) {
        int m = b*49 + q;
        int k2 = l + 32;
        bool v2 = k2 < 49;
        float g1 = g_gate[(size_t)m*49 + l];
        float g2 = v2 ? g_gate[(size_t)m*49 + k2] : 0.f;
        const float* qr  = Qt + q*65;
        const float* k1r = Kt + l*65;
        const float* k2r = Kt + (v2 ? k2 : l)*65;
        float d1 = 0.f, d2 = 0.f;
#pragma unroll 8
        for (int d = 0; d < 64; d++) {
            float qv = qr[d];
            d1 += qv * k1r[d];
            d2 += qv * k2r[d];
        }
        float lv1 = d1*SCALEV_*(1.f + g1);
        float lv2 = v2 ? d2*SCALEV_*(1.f + g2) : -1e30f;
        float mx = fmaxf(lv1, lv2);
#pragma unroll
        for (int o = 16; o > 0; o >>= 1) mx = fmaxf(mx, __shfl_xor_sync(0xffffffffu, mx, o));
        float e1 = expf(lv1 - mx);
        float e2 = v2 ? expf(lv2 - mx) : 0.f;
        float ssum = wsum(e1 + e2);
        float inv = 1.f / ssum;
        wrow[w][l] = e1 * inv;
        if (v2) wrow[w][k2] = e2 * inv;
        __syncwarp();
        float a1 = 0.f, a2 = 0.f;
        for (int k = 0; k < 49; k++) {
            float wk = wrow[w][k];
            a1 += wk * Vt[k*65 + l];
            a2 += wk * Vt[k*65 + l + 32];
        }
        out[(size_t)m*512 + h*64 + l]      = to_tf32(a1);
        out[(size_t)m*512 + h*64 + l + 32] = to_tf32(a2);
        __syncwarp();
    }
}

// ---------------- launch ----------------
extern "C" void kernel_launch(void* const* d_in, const int* in_sizes, int n_in,
                              void* d_out, int out_size) {
    const float* Q     = (const float*)d_in[0];
    const float* Kin   = (const float*)d_in[1];
    const float* Vin   = (const float*)d_in[2];
    const float* Wq    = (const float*)d_in[3];
    const float* bq    = (const float*)d_in[4];
    const float* Wk    = (const float*)d_in[5];
    const float* bk    = (const float*)d_in[6];
    const float* Wv    = (const float*)d_in[7];
    const float* bv    = (const float*)d_in[8];
    const float* Wo    = (const float*)d_in[9];
    const float* bo    = (const float*)d_in[10];
    const float* rel   = (const float*)d_in[11];
    const float* Wproj = (const float*)d_in[12];
    const float* bproj = (const float*)d_in[13];
    const float* Wgate = (const float*)d_in[14];
    const float* bgate = (const float*)d_in[15];
    const float* Wc1   = (const float*)d_in[16];
    const float* bc1   = (const float*)d_in[17];
    const float* gc    = (const float*)d_in[18];
    const float* bcln  = (const float*)d_in[19];
    const float* Wc2   = (const float*)d_in[20];
    const float* bc2   = (const float*)d_in[21];
    const float* Wr1   = (const float*)d_in[22];
    const float* br1   = (const float*)d_in[23];
    const float* gr    = (const float*)d_in[24];
    const float* brln  = (const float*)d_in[25];
    const float* Wr2   = (const float*)d_in[26];
    const float* br2   = (const float*)d_in[27];
    const float* convW = (const float*)d_in[28];
    const float* convb = (const float*)d_in[29];

    void *p_qr, *p_att, *p_convWt, *p_Wor;
    cudaGetSymbolAddress(&p_qr, g_qr);
    cudaGetSymbolAddress(&p_att, g_att);
    cudaGetSymbolAddress(&p_convWt, g_convWt);
    cudaGetSymbolAddress(&p_Wor, g_Wor);

    static bool attr_set = false;
    if (!attr_set) {
        cudaFuncSetAttribute(rea_gconv, cudaFuncAttributeMaxDynamicSharedMemorySize, GEMM_SMEM);
        cudaFuncSetAttribute(rea_gqkv, cudaFuncAttributeMaxDynamicSharedMemorySize, GEMM_SMEM);
        cudaFuncSetAttribute(rea_gout, cudaFuncAttributeMaxDynamicSharedMemorySize, GEMM_SMEM);
        attr_set = true;
    }

    // 6 launches; ncu captures launch idx 3 => rea_pair (v5) this round
    rea_prologue<<<3665, 256>>>(convW, Q, Wr2, Wproj, Wgate, rel, br2, bproj, bgate,
                                Wq, Wk, Wc1, Wr1, bq, bk, Wv, Wo);
    rea_gconv<<<dim3(4, 13, 9), 128, GEMM_SMEM>>>((const float*)p_qr,
                                                  (const float*)p_convWt, convb);
    rea_gqkv<<<296, 128, GEMM_SMEM>>>(bv, Q, Kin, Vin);

    rea_pair<<<dim3(32, 10), 256>>>(Wc2, bc1, gc, bcln, bc2, br1, gr, brln);

    rea_attn<<<dim3(8, 32), 256>>>((float*)p_att, (float*)d_out);

    rea_gout<<<dim3(4, 13, 4), 128, GEMM_SMEM>>>((const float*)p_att, (const float*)p_Wor,
                                                 bo, (float*)d_out);
}